// round 1
// baseline (speedup 1.0000x reference)
#include <cuda_runtime.h>
#include <cuda_bf16.h>
#include <math.h>

// Problem dims
#define BB   64
#define PP   196
#define ENCD 2048
#define HD   1024
#define AD   1024
#define ED   512
#define VD   10000
#define TCD  32
#define TD   31           // TC-1
#define XD   (ED+ENCD)    // 2560
#define G4H  (4*HD)       // 4096

// Output layout offsets (float32 elements)
#define O_PRED  0L
#define N_PRED  ((long)BB*TD*VD)                 // 19,840,000
#define O_ALPHA (N_PRED)                          // 19,840,000
#define N_ALPHA ((long)BB*TD*PP)                 // 388,864
#define O_CAPS  (O_ALPHA + N_ALPHA)              // 20,228,864
#define O_DLEN  (O_CAPS + (long)BB*TCD)          // 20,230,912
#define O_IND   (O_DLEN + BB)                    // 20,230,976

// -------- scratch (device globals; no allocations allowed) --------
__device__ int   g_ind[BB];
__device__ int   g_declens[BB];
__device__ int   g_caps[BB*TCD];
__device__ int   g_rowmap[BB*PP];
__device__ float g_mean[BB*ENCD];
__device__ float g_h[BB*HD];
__device__ float g_c[BB*HD];
__device__ float g_hnew[BB*HD];
__device__ float g_dec[BB*AD];
__device__ float g_alpha[BB*PP];
__device__ float g_ctx[BB*ENCD];
__device__ float g_x[BB*XD];
__device__ float g_gates[BB*G4H];
__device__ float g_encatt[(long)BB*PP*AD];       // 51.4 MB

// ---------------------------------------------------------------
// Sort: stable descending by lengths (matches jnp.argsort(-lengths))
// Also emits caps / dec_lens / ind outputs.
// ---------------------------------------------------------------
__global__ void sort_kernel(const int* __restrict__ lengths,
                            const int* __restrict__ caps_in,
                            float* __restrict__ out)
{
    int b = threadIdx.x;
    if (b < BB) {
        int len = lengths[b];
        int rank = 0;
        for (int b2 = 0; b2 < BB; b2++) {
            int l2 = lengths[b2];
            rank += (l2 > len) || (l2 == len && b2 < b);
        }
        g_ind[rank] = b;
    }
    __syncthreads();
    if (b < BB) {
        int i = g_ind[b];
        int dl = lengths[i] - 1;
        g_declens[b] = dl;
        out[O_DLEN + b] = (float)dl;
        out[O_IND  + b] = (float)i;
        for (int j = 0; j < TCD; j++) {
            int cv = caps_in[i*TCD + j];
            g_caps[b*TCD + j] = cv;
            out[O_CAPS + b*TCD + j] = (float)cv;
        }
    }
}

__global__ void rowmap_kernel()
{
    int m = blockIdx.x*blockDim.x + threadIdx.x;
    if (m < BB*PP) g_rowmap[m] = g_ind[m/PP]*PP + (m%PP);
}

// mean over P of gathered enc_out
__global__ void mean_kernel(const float* __restrict__ enc_out)
{
    int e = blockIdx.x*blockDim.x + threadIdx.x;
    int b = blockIdx.y;
    if (e >= ENCD) return;
    long base = ((long)g_ind[b]*PP)*ENCD + e;
    float acc = 0.f;
    for (int p = 0; p < PP; p++) acc += enc_out[base + (long)p*ENCD];
    g_mean[b*ENCD + e] = acc / (float)PP;
}

// ---------------------------------------------------------------
// Templated SGEMM:  C = A(MxK) * W(NxK)^T + bias  with epilogues
//  EPI 0: write            C[m,n] = v
//  EPI 1: accumulate       C[m,n] += v
//  EPI 2: awe              C[m,n] = sigmoid(v) * extra[m*N+n]
//  EPI 3: masked write     C[m,n] = v * (t < declens[m])
// rowmap (optional): source row of A for logical row m
// ---------------------------------------------------------------
template<int BM,int BN,int BK,int TM,int TN,int EPI>
__global__ __launch_bounds__((BM/TM)*(BN/TN))
void sgemm_kernel(const float* __restrict__ A, const int* __restrict__ rowmap, int lda,
                  const float* __restrict__ W, int ldw,
                  const float* __restrict__ bias,
                  float* __restrict__ C, int ldc,
                  int M, int N, int K,
                  const float* __restrict__ extra,
                  const int* __restrict__ declens, int t)
{
    constexpr int NT = (BM/TM)*(BN/TN);
    __shared__ float As[BK][BM+4];
    __shared__ float Ws[BK][BN+4];

    const int tid = threadIdx.x;
    const int m0 = blockIdx.y*BM, n0 = blockIdx.x*BN;
    const int tx = tid % (BN/TN);
    const int ty = tid / (BN/TN);

    float acc[TM][TN];
    #pragma unroll
    for (int i=0;i<TM;i++)
        #pragma unroll
        for (int j=0;j<TN;j++) acc[i][j]=0.f;

    for (int k0 = 0; k0 < K; k0 += BK) {
        // load A tile (float4 along K)
        for (int s = tid; s < BM*(BK/4); s += NT) {
            int r  = s / (BK/4);
            int kk = (s % (BK/4))*4;
            int row = m0 + r;
            float4 v = make_float4(0.f,0.f,0.f,0.f);
            if (row < M) {
                long src = rowmap ? ((long)rowmap[row]*lda) : ((long)row*lda);
                v = *reinterpret_cast<const float4*>(A + src + k0 + kk);
            }
            As[kk+0][r]=v.x; As[kk+1][r]=v.y; As[kk+2][r]=v.z; As[kk+3][r]=v.w;
        }
        // load W tile
        for (int s = tid; s < BN*(BK/4); s += NT) {
            int r  = s / (BK/4);
            int kk = (s % (BK/4))*4;
            int row = n0 + r;
            float4 v = make_float4(0.f,0.f,0.f,0.f);
            if (row < N)
                v = *reinterpret_cast<const float4*>(W + (long)row*ldw + k0 + kk);
            Ws[kk+0][r]=v.x; Ws[kk+1][r]=v.y; Ws[kk+2][r]=v.z; Ws[kk+3][r]=v.w;
        }
        __syncthreads();
        #pragma unroll
        for (int k=0;k<BK;k++) {
            float af[TM], wf[TN];
            #pragma unroll
            for (int i=0;i<TM;i++) af[i] = As[k][ty*TM+i];
            #pragma unroll
            for (int j=0;j<TN;j++) wf[j] = Ws[k][tx*TN+j];
            #pragma unroll
            for (int i=0;i<TM;i++)
                #pragma unroll
                for (int j=0;j<TN;j++) acc[i][j] = fmaf(af[i], wf[j], acc[i][j]);
        }
        __syncthreads();
    }

    #pragma unroll
    for (int i=0;i<TM;i++) {
        int m = m0 + ty*TM + i;
        if (m >= M) continue;
        float mf = 1.f;
        if (EPI == 3) mf = (t < declens[m]) ? 1.f : 0.f;
        #pragma unroll
        for (int j=0;j<TN;j++) {
            int n = n0 + tx*TN + j;
            if (n >= N) continue;
            float v = acc[i][j] + bias[n];
            long ci = (long)m*ldc + n;
            if      (EPI == 0) C[ci] = v;
            else if (EPI == 1) C[ci] += v;
            else if (EPI == 2) C[ci] = (1.f/(1.f+expf(-v))) * extra[(long)m*N + n];
            else               C[ci] = v * mf;
        }
    }
}

template<int BM,int BN,int BK,int TM,int TN,int EPI>
static inline void sgemm(const float*A,const int*rowmap,int lda,
                         const float*W,int ldw,const float*bias,
                         float*C,int ldc,int M,int N,int K,
                         const float*extra,const int*declens,int t)
{
    dim3 grid((N+BN-1)/BN, (M+BM-1)/BM);
    sgemm_kernel<BM,BN,BK,TM,TN,EPI><<<grid,(BM/TM)*(BN/TN)>>>(
        A,rowmap,lda,W,ldw,bias,C,ldc,M,N,K,extra,declens,t);
}

// ---------------------------------------------------------------
// Fused attention scores + softmax. One block (512 thr) per batch row.
//   a[p] = sum_a relu(encatt[b,p,a] + dec[b,a]) * Wfull[a] + bfull
//   alpha = softmax_p(a);  also writes alpha*mask to output alphas.
// ---------------------------------------------------------------
__global__ __launch_bounds__(512)
void att_softmax_kernel(const float* __restrict__ wfull,
                        const float* __restrict__ bfull,
                        float* __restrict__ out_alphas, int t)
{
    __shared__ float s_dec[AD];
    __shared__ float s_wf[AD];
    __shared__ float s_sc[PP];
    __shared__ float s_red[16];

    const int b = blockIdx.x;
    const int tid = threadIdx.x;
    const int warp = tid >> 5, lane = tid & 31;

    for (int i = tid; i < AD; i += 512) {
        s_dec[i] = g_dec[b*AD + i];
        s_wf[i]  = wfull[i];
    }
    __syncthreads();

    const float bf = bfull[0];
    for (int p = warp; p < PP; p += 16) {
        const float* row = g_encatt + ((long)b*PP + p)*AD;
        float acc = 0.f;
        for (int a = lane; a < AD; a += 32) {
            float v = row[a] + s_dec[a];
            v = v > 0.f ? v : 0.f;
            acc = fmaf(v, s_wf[a], acc);
        }
        #pragma unroll
        for (int o = 16; o > 0; o >>= 1) acc += __shfl_down_sync(0xffffffffu, acc, o);
        if (lane == 0) s_sc[p] = acc + bf;
    }
    __syncthreads();

    // softmax over PP values
    float v = (tid < PP) ? s_sc[tid] : -INFINITY;
    float m = v;
    #pragma unroll
    for (int o = 16; o > 0; o >>= 1) m = fmaxf(m, __shfl_xor_sync(0xffffffffu, m, o));
    if (lane == 0) s_red[warp] = m;
    __syncthreads();
    if (warp == 0) {
        float mm = (lane < 16) ? s_red[lane] : -INFINITY;
        #pragma unroll
        for (int o = 8; o > 0; o >>= 1) mm = fmaxf(mm, __shfl_xor_sync(0xffffffffu, mm, o));
        if (lane == 0) s_red[0] = mm;
    }
    __syncthreads();
    const float bmax = s_red[0];
    float e = (tid < PP) ? expf(v - bmax) : 0.f;
    float s = e;
    #pragma unroll
    for (int o = 16; o > 0; o >>= 1) s += __shfl_xor_sync(0xffffffffu, s, o);
    __syncthreads();
    if (lane == 0) s_red[warp] = s;
    __syncthreads();
    if (warp == 0) {
        float ss = (lane < 16) ? s_red[lane] : 0.f;
        #pragma unroll
        for (int o = 8; o > 0; o >>= 1) ss += __shfl_xor_sync(0xffffffffu, ss, o);
        if (lane == 0) s_red[0] = ss;
    }
    __syncthreads();
    const float inv = 1.f / s_red[0];
    if (tid < PP) {
        float al = e * inv;
        g_alpha[b*PP + tid] = al;
        float mf = (t < g_declens[b]) ? 1.f : 0.f;
        out_alphas[((long)b*TD + t)*PP + tid] = al * mf;
    }
}

// context[b,e] = sum_p eo[b,p,e] * alpha[b,p]
__global__ void ctx_kernel(const float* __restrict__ enc_out)
{
    __shared__ float s_al[PP];
    const int b = blockIdx.y;
    const int tid = threadIdx.x;
    if (tid < PP) s_al[tid] = g_alpha[b*PP + tid];
    __syncthreads();
    int e = blockIdx.x*blockDim.x + tid;
    if (e >= ENCD) return;
    long base = ((long)g_ind[b]*PP)*ENCD + e;
    float acc = 0.f;
    #pragma unroll 4
    for (int p = 0; p < PP; p++)
        acc = fmaf(enc_out[base + (long)p*ENCD], s_al[p], acc);
    g_ctx[b*ENCD + e] = acc;
}

// x[:, 0:E] = emb[caps[b, t]]
__global__ void xemb_kernel(const float* __restrict__ emb, int t)
{
    int idx = blockIdx.x*blockDim.x + threadIdx.x;
    if (idx >= BB*ED) return;
    int b = idx / ED, j = idx % ED;
    int cap = g_caps[b*TCD + t];
    g_x[b*XD + j] = emb[(long)cap*ED + j];
}

// LSTM cell + masked state update
__global__ void lstm_kernel(int t)
{
    int idx = blockIdx.x*blockDim.x + threadIdx.x;
    if (idx >= BB*HD) return;
    int b = idx / HD, j = idx % HD;
    long base = (long)b*G4H;
    float gi = g_gates[base + j];
    float gf = g_gates[base + HD + j];
    float gg = g_gates[base + 2*HD + j];
    float go = g_gates[base + 3*HD + j];
    float si = 1.f/(1.f+expf(-gi));
    float sf = 1.f/(1.f+expf(-gf));
    float so = 1.f/(1.f+expf(-go));
    float cn = sf * g_c[idx] + si * tanhf(gg);
    float hn = so * tanhf(cn);
    g_hnew[idx] = hn;
    if (t < g_declens[b]) { g_h[idx] = hn; g_c[idx] = cn; }
}

// ---------------------------------------------------------------
extern "C" void kernel_launch(void* const* d_in, const int* in_sizes, int n_in,
                              void* d_out, int out_size)
{
    const float* enc_out  = (const float*)d_in[0];
    const int*   caps_in  = (const int*)  d_in[1];
    const int*   lengths  = (const int*)  d_in[2];
    const float* W_enc    = (const float*)d_in[3];
    const float* b_enc    = (const float*)d_in[4];
    const float* W_dec    = (const float*)d_in[5];
    const float* b_dec    = (const float*)d_in[6];
    const float* W_full   = (const float*)d_in[7];
    const float* b_full   = (const float*)d_in[8];
    const float* emb      = (const float*)d_in[9];
    const float* W_ih     = (const float*)d_in[10];
    const float* b_ih     = (const float*)d_in[11];
    const float* W_hh     = (const float*)d_in[12];
    const float* b_hh     = (const float*)d_in[13];
    const float* W_init_h = (const float*)d_in[14];
    const float* b_init_h = (const float*)d_in[15];
    const float* W_init_c = (const float*)d_in[16];
    const float* b_init_c = (const float*)d_in[17];
    const float* W_beta   = (const float*)d_in[18];
    const float* b_beta   = (const float*)d_in[19];
    const float* W_fc     = (const float*)d_in[20];
    const float* b_fc     = (const float*)d_in[21];
    float* out = (float*)d_out;

    // scratch addresses
    int *p_ind, *p_declens, *p_rowmap;
    float *p_mean,*p_h,*p_c,*p_hnew,*p_dec,*p_ctx,*p_x,*p_gates,*p_encatt;
    cudaGetSymbolAddress((void**)&p_ind,     g_ind);
    cudaGetSymbolAddress((void**)&p_declens, g_declens);
    cudaGetSymbolAddress((void**)&p_rowmap,  g_rowmap);
    cudaGetSymbolAddress((void**)&p_mean,    g_mean);
    cudaGetSymbolAddress((void**)&p_h,       g_h);
    cudaGetSymbolAddress((void**)&p_c,       g_c);
    cudaGetSymbolAddress((void**)&p_hnew,    g_hnew);
    cudaGetSymbolAddress((void**)&p_dec,     g_dec);
    cudaGetSymbolAddress((void**)&p_ctx,     g_ctx);
    cudaGetSymbolAddress((void**)&p_x,       g_x);
    cudaGetSymbolAddress((void**)&p_gates,   g_gates);
    cudaGetSymbolAddress((void**)&p_encatt,  g_encatt);

    // prologue
    sort_kernel<<<1, 64>>>(lengths, caps_in, out);
    rowmap_kernel<<<(BB*PP + 255)/256, 256>>>();
    mean_kernel<<<dim3(ENCD/256, BB), 256>>>(enc_out);

    // h0 / c0  : (64 x 1024) = mean(64x2048) @ W_init^T
    sgemm<64,64,16,4,4,0>(p_mean,nullptr,ENCD, W_init_h,ENCD,b_init_h, p_h,HD, BB,HD,ENCD, nullptr,nullptr,0);
    sgemm<64,64,16,4,4,0>(p_mean,nullptr,ENCD, W_init_c,ENCD,b_init_c, p_c,HD, BB,HD,ENCD, nullptr,nullptr,0);

    // enc_att : (12544 x 1024) = eo(12544x2048) @ W_enc^T   (gather via rowmap)
    sgemm<128,128,16,8,8,0>(enc_out,p_rowmap,ENCD, W_enc,ENCD,b_enc, p_encatt,AD, BB*PP,AD,ENCD, nullptr,nullptr,0);

    for (int t = 0; t < TD; t++) {
        // dec = h @ W_dec^T + b
        sgemm<64,64,16,4,4,0>(p_h,nullptr,HD, W_dec,HD,b_dec, p_dec,AD, BB,AD,HD, nullptr,nullptr,0);
        // attention + softmax (+ write masked alphas to output)
        att_softmax_kernel<<<BB, 512>>>(W_full, b_full, out + O_ALPHA, t);
        // context
        ctx_kernel<<<dim3(ENCD/256, BB), 256>>>(enc_out);
        // x = [emb_t , sigmoid(h@W_beta^T+b)*context]
        xemb_kernel<<<(BB*ED + 255)/256, 256>>>(emb, t);
        sgemm<64,64,16,4,4,2>(p_h,nullptr,HD, W_beta,HD,b_beta, p_x+ED,XD, BB,ENCD,HD, p_ctx,nullptr,0);
        // gates = x@W_ih^T + b_ih  (+=)  h@W_hh^T + b_hh
        sgemm<64,64,16,4,4,0>(p_x,nullptr,XD, W_ih,XD,b_ih, p_gates,G4H, BB,G4H,XD, nullptr,nullptr,0);
        sgemm<64,64,16,4,4,1>(p_h,nullptr,HD, W_hh,HD,b_hh, p_gates,G4H, BB,G4H,HD, nullptr,nullptr,0);
        // LSTM cell + masked carry
        lstm_kernel<<<(BB*HD + 255)/256, 256>>>(t);
        // preds = (h_new @ W_fc^T + b_fc) * mask  -> written straight to out
        sgemm<64,64,16,4,4,3>(p_hnew,nullptr,HD, W_fc,HD,b_fc, out + (long)t*VD, TD*VD,
                              BB,VD,HD, nullptr,p_declens,t);
    }
}

// round 2
// speedup vs baseline: 1.2512x; 1.2512x over previous
#include <cuda_runtime.h>
#include <cuda_bf16.h>
#include <math.h>

// Problem dims
#define BB   64
#define PP   196
#define ENCD 2048
#define HD   1024
#define AD   1024
#define ED   512
#define VD   10000
#define TCD  32
#define TD   31           // TC-1
#define XD   (ED+ENCD)    // 2560
#define G4H  (4*HD)       // 4096
#define MB   (TD*BB)      // 1984 batched rows (time-major: row = t*BB + b)

// Output layout offsets (float32 elements)
#define O_PRED  0L
#define N_PRED  ((long)BB*TD*VD)
#define O_ALPHA (N_PRED)
#define N_ALPHA ((long)BB*TD*PP)
#define O_CAPS  (O_ALPHA + N_ALPHA)
#define O_DLEN  (O_CAPS + (long)BB*TCD)
#define O_IND   (O_DLEN + BB)

// -------- scratch (device globals; no allocations allowed) --------
__device__ int   g_ind[BB];
__device__ int   g_declens[BB];
__device__ int   g_caps[BB*TCD];
__device__ int   g_rowmap[BB*PP];
__device__ float g_mean[BB*ENCD];
__device__ float g_h[BB*HD];
__device__ float g_c[BB*HD];
__device__ float g_hall[(long)MB*HD];            // h_new for all t (time-major)
__device__ float g_dec[BB*AD];
__device__ float g_betapre[BB*ENCD];
__device__ float g_alpha[BB*PP];
__device__ float g_awe[BB*ENCD];
__device__ float g_gates[BB*G4H];
__device__ float g_embt[(long)MB*ED];            // gathered embeddings, all t
__device__ float g_P[(long)MB*G4H];              // emb@W_ih_e^T + b_ih + b_hh
__device__ float g_bias_ihh[G4H];
__device__ float g_zero[G4H];                    // static zeros
__device__ float g_encatt[(long)BB*PP*AD];       // 51.4 MB

// ---------------------------------------------------------------
// Sort: stable descending by lengths (matches jnp.argsort(-lengths))
// ---------------------------------------------------------------
__global__ void sort_kernel(const int* __restrict__ lengths,
                            const int* __restrict__ caps_in,
                            float* __restrict__ out)
{
    int b = threadIdx.x;
    if (b < BB) {
        int len = lengths[b];
        int rank = 0;
        for (int b2 = 0; b2 < BB; b2++) {
            int l2 = lengths[b2];
            rank += (l2 > len) || (l2 == len && b2 < b);
        }
        g_ind[rank] = b;
    }
    __syncthreads();
    if (b < BB) {
        int i = g_ind[b];
        int dl = lengths[i] - 1;
        g_declens[b] = dl;
        out[O_DLEN + b] = (float)dl;
        out[O_IND  + b] = (float)i;
        for (int j = 0; j < TCD; j++) {
            int cv = caps_in[i*TCD + j];
            g_caps[b*TCD + j] = cv;
            out[O_CAPS + b*TCD + j] = (float)cv;
        }
    }
}

__global__ void rowmap_kernel()
{
    int m = blockIdx.x*blockDim.x + threadIdx.x;
    if (m < BB*PP) g_rowmap[m] = g_ind[m/PP]*PP + (m%PP);
}

__global__ void bias_combine_kernel(const float* __restrict__ b_ih,
                                    const float* __restrict__ b_hh)
{
    int n = blockIdx.x*blockDim.x + threadIdx.x;
    if (n < G4H) g_bias_ihh[n] = b_ih[n] + b_hh[n];
}

// gather embeddings for all (t, b): row = t*BB + b
__global__ void embt_kernel(const float* __restrict__ emb)
{
    long idx = (long)blockIdx.x*blockDim.x + threadIdx.x;
    if (idx >= (long)MB*ED) return;
    int row = (int)(idx / ED), j = (int)(idx % ED);
    int t = row / BB, b = row % BB;
    int cap = g_caps[b*TCD + t];
    g_embt[idx] = emb[(long)cap*ED + j];
}

// mean over P of gathered enc_out
__global__ void mean_kernel(const float* __restrict__ enc_out)
{
    int e = blockIdx.x*blockDim.x + threadIdx.x;
    int b = blockIdx.y;
    if (e >= ENCD) return;
    long base = ((long)g_ind[b]*PP)*ENCD + e;
    float acc = 0.f;
    for (int p = 0; p < PP; p++) acc += enc_out[base + (long)p*ENCD];
    g_mean[b*ENCD + e] = acc / (float)PP;
}

// ---------------------------------------------------------------
// Templated SGEMM:  C = A(MxK) * W(NxK)^T + bias  with epilogues
//  EPI 0: write            C[m,n] = v
//  EPI 1: accumulate       C[m,n] += v
//  EPI 4: batched preds    out[((m%BB)*TD + m/BB)*ldc + n] = v * mask
// ---------------------------------------------------------------
template<int BM,int BN,int BK,int TM,int TN,int EPI>
__global__ __launch_bounds__((BM/TM)*(BN/TN))
void sgemm_kernel(const float* __restrict__ A, const int* __restrict__ rowmap, int lda,
                  const float* __restrict__ W, int ldw,
                  const float* __restrict__ bias,
                  float* __restrict__ C, int ldc,
                  int M, int N, int K,
                  const int* __restrict__ declens)
{
    constexpr int NT = (BM/TM)*(BN/TN);
    __shared__ float As[BK][BM+4];
    __shared__ float Ws[BK][BN+4];

    const int tid = threadIdx.x;
    const int m0 = blockIdx.y*BM, n0 = blockIdx.x*BN;
    const int tx = tid % (BN/TN);
    const int ty = tid / (BN/TN);

    float acc[TM][TN];
    #pragma unroll
    for (int i=0;i<TM;i++)
        #pragma unroll
        for (int j=0;j<TN;j++) acc[i][j]=0.f;

    for (int k0 = 0; k0 < K; k0 += BK) {
        for (int s = tid; s < BM*(BK/4); s += NT) {
            int r  = s / (BK/4);
            int kk = (s % (BK/4))*4;
            int row = m0 + r;
            float4 v = make_float4(0.f,0.f,0.f,0.f);
            if (row < M) {
                long src = rowmap ? ((long)rowmap[row]*lda) : ((long)row*lda);
                v = *reinterpret_cast<const float4*>(A + src + k0 + kk);
            }
            As[kk+0][r]=v.x; As[kk+1][r]=v.y; As[kk+2][r]=v.z; As[kk+3][r]=v.w;
        }
        for (int s = tid; s < BN*(BK/4); s += NT) {
            int r  = s / (BK/4);
            int kk = (s % (BK/4))*4;
            int row = n0 + r;
            float4 v = make_float4(0.f,0.f,0.f,0.f);
            if (row < N)
                v = *reinterpret_cast<const float4*>(W + (long)row*ldw + k0 + kk);
            Ws[kk+0][r]=v.x; Ws[kk+1][r]=v.y; Ws[kk+2][r]=v.z; Ws[kk+3][r]=v.w;
        }
        __syncthreads();
        #pragma unroll
        for (int k=0;k<BK;k++) {
            float af[TM], wf[TN];
            #pragma unroll
            for (int i=0;i<TM;i++) af[i] = As[k][ty*TM+i];
            #pragma unroll
            for (int j=0;j<TN;j++) wf[j] = Ws[k][tx*TN+j];
            #pragma unroll
            for (int i=0;i<TM;i++)
                #pragma unroll
                for (int j=0;j<TN;j++) acc[i][j] = fmaf(af[i], wf[j], acc[i][j]);
        }
        __syncthreads();
    }

    #pragma unroll
    for (int i=0;i<TM;i++) {
        int m = m0 + ty*TM + i;
        if (m >= M) continue;
        float mf = 1.f;
        int bb = 0, tt = 0;
        if (EPI == 4) {
            bb = m % BB; tt = m / BB;
            mf = (tt < declens[bb]) ? 1.f : 0.f;
        }
        #pragma unroll
        for (int j=0;j<TN;j++) {
            int n = n0 + tx*TN + j;
            if (n >= N) continue;
            float v = acc[i][j] + bias[n];
            if      (EPI == 0) C[(long)m*ldc + n] = v;
            else if (EPI == 1) C[(long)m*ldc + n] += v;
            else               C[((long)bb*TD + tt)*ldc + n] = v * mf;
        }
    }
}

template<int BM,int BN,int BK,int TM,int TN,int EPI>
static inline void sgemm(const float*A,const int*rowmap,int lda,
                         const float*W,int ldw,const float*bias,
                         float*C,int ldc,int M,int N,int K,
                         const int*declens)
{
    dim3 grid((N+BN-1)/BN, (M+BM-1)/BM);
    sgemm_kernel<BM,BN,BK,TM,TN,EPI><<<grid,(BM/TM)*(BN/TN)>>>(
        A,rowmap,lda,W,ldw,bias,C,ldc,M,N,K,declens);
}

// ---------------------------------------------------------------
// Fused h-GEMM: A = g_h (64x1024), weights = [W_dec | W_beta | W_hh]
// concatenated along N (1024 + 2048 + 4096 = 7168).
//   n in [0,1024):    g_dec     = h@W_dec^T  + b_dec
//   n in [1024,3072): g_betapre = h@W_beta^T + b_beta
//   n in [3072,7168): g_gates   = h@W_hh^T   + P_t      (P_t has b_ih+b_hh folded)
// BM=64, BN=32, BK=16, TM=4, TN=4, 128 threads, grid = 224 blocks.
// ---------------------------------------------------------------
#define HG_BN 32
#define HG_BK 16
__global__ __launch_bounds__(128)
void hgemm_kernel(const float* __restrict__ Wdec,
                  const float* __restrict__ Wbeta,
                  const float* __restrict__ Whh,
                  const float* __restrict__ bdec,
                  const float* __restrict__ bbeta,
                  const float* __restrict__ Pt)
{
    __shared__ float As[HG_BK][BB+4];
    __shared__ float Ws[HG_BK][HG_BN+4];

    const int tid = threadIdx.x;
    const int n0 = blockIdx.x*HG_BN;
    const int tx = tid % 8;     // BN/TN
    const int ty = tid / 8;     // BM/TM = 16

    float acc[4][4];
    #pragma unroll
    for (int i=0;i<4;i++)
        #pragma unroll
        for (int j=0;j<4;j++) acc[i][j]=0.f;

    for (int k0 = 0; k0 < HD; k0 += HG_BK) {
        // A tile: 64 rows x 16 k  (256 float4 slots / 128 threads = 2 iters)
        for (int s = tid; s < BB*(HG_BK/4); s += 128) {
            int r  = s / (HG_BK/4);
            int kk = (s % (HG_BK/4))*4;
            float4 v = *reinterpret_cast<const float4*>(g_h + (long)r*HD + k0 + kk);
            As[kk+0][r]=v.x; As[kk+1][r]=v.y; As[kk+2][r]=v.z; As[kk+3][r]=v.w;
        }
        // W tile: 32 rows x 16 k
        for (int s = tid; s < HG_BN*(HG_BK/4); s += 128) {
            int r  = s / (HG_BK/4);
            int kk = (s % (HG_BK/4))*4;
            int gn = n0 + r;
            const float* wrow;
            if (gn < 1024)      wrow = Wdec  + (long)gn*HD;
            else if (gn < 3072) wrow = Wbeta + (long)(gn-1024)*HD;
            else                wrow = Whh   + (long)(gn-3072)*HD;
            float4 v = *reinterpret_cast<const float4*>(wrow + k0 + kk);
            Ws[kk+0][r]=v.x; Ws[kk+1][r]=v.y; Ws[kk+2][r]=v.z; Ws[kk+3][r]=v.w;
        }
        __syncthreads();
        #pragma unroll
        for (int k=0;k<HG_BK;k++) {
            float af[4], wf[4];
            #pragma unroll
            for (int i=0;i<4;i++) af[i] = As[k][ty*4+i];
            #pragma unroll
            for (int j=0;j<4;j++) wf[j] = Ws[k][tx*4+j];
            #pragma unroll
            for (int i=0;i<4;i++)
                #pragma unroll
                for (int j=0;j<4;j++) acc[i][j] = fmaf(af[i], wf[j], acc[i][j]);
        }
        __syncthreads();
    }

    #pragma unroll
    for (int i=0;i<4;i++) {
        int m = ty*4 + i;
        #pragma unroll
        for (int j=0;j<4;j++) {
            int n = n0 + tx*4 + j;
            float v = acc[i][j];
            if (n < 1024)      g_dec[m*AD + n]               = v + bdec[n];
            else if (n < 3072) g_betapre[m*ENCD + (n-1024)]  = v + bbeta[n-1024];
            else {
                int nn = n - 3072;
                g_gates[m*G4H + nn] = v + Pt[(long)m*G4H + nn];
            }
        }
    }
}

// ---------------------------------------------------------------
// Fused attention scores + softmax (one block / batch row)
// ---------------------------------------------------------------
__global__ __launch_bounds__(512)
void att_softmax_kernel(const float* __restrict__ wfull,
                        const float* __restrict__ bfull,
                        float* __restrict__ out_alphas, int t)
{
    __shared__ float s_dec[AD];
    __shared__ float s_wf[AD];
    __shared__ float s_sc[PP];
    __shared__ float s_red[16];

    const int b = blockIdx.x;
    const int tid = threadIdx.x;
    const int warp = tid >> 5, lane = tid & 31;

    for (int i = tid; i < AD; i += 512) {
        s_dec[i] = g_dec[b*AD + i];
        s_wf[i]  = wfull[i];
    }
    __syncthreads();

    const float bf = bfull[0];
    for (int p = warp; p < PP; p += 16) {
        const float* row = g_encatt + ((long)b*PP + p)*AD;
        float acc = 0.f;
        for (int a = lane; a < AD; a += 32) {
            float v = row[a] + s_dec[a];
            v = v > 0.f ? v : 0.f;
            acc = fmaf(v, s_wf[a], acc);
        }
        #pragma unroll
        for (int o = 16; o > 0; o >>= 1) acc += __shfl_down_sync(0xffffffffu, acc, o);
        if (lane == 0) s_sc[p] = acc + bf;
    }
    __syncthreads();

    float v = (tid < PP) ? s_sc[tid] : -INFINITY;
    float m = v;
    #pragma unroll
    for (int o = 16; o > 0; o >>= 1) m = fmaxf(m, __shfl_xor_sync(0xffffffffu, m, o));
    if (lane == 0) s_red[warp] = m;
    __syncthreads();
    if (warp == 0) {
        float mm = (lane < 16) ? s_red[lane] : -INFINITY;
        #pragma unroll
        for (int o = 8; o > 0; o >>= 1) mm = fmaxf(mm, __shfl_xor_sync(0xffffffffu, mm, o));
        if (lane == 0) s_red[0] = mm;
    }
    __syncthreads();
    const float bmax = s_red[0];
    float e = (tid < PP) ? expf(v - bmax) : 0.f;
    float s = e;
    #pragma unroll
    for (int o = 16; o > 0; o >>= 1) s += __shfl_xor_sync(0xffffffffu, s, o);
    __syncthreads();
    if (lane == 0) s_red[warp] = s;
    __syncthreads();
    if (warp == 0) {
        float ss = (lane < 16) ? s_red[lane] : 0.f;
        #pragma unroll
        for (int o = 8; o > 0; o >>= 1) ss += __shfl_xor_sync(0xffffffffu, ss, o);
        if (lane == 0) s_red[0] = ss;
    }
    __syncthreads();
    const float inv = 1.f / s_red[0];
    if (tid < PP) {
        float al = e * inv;
        g_alpha[b*PP + tid] = al;
        float mf = (t < g_declens[b]) ? 1.f : 0.f;
        out_alphas[((long)b*TD + t)*PP + tid] = al * mf;
    }
}

// context + fused awe: awe[b,e] = sigmoid(betapre[b,e]) * sum_p eo*alpha
__global__ void ctx_awe_kernel(const float* __restrict__ enc_out)
{
    __shared__ float s_al[PP];
    const int b = blockIdx.y;
    const int tid = threadIdx.x;
    if (tid < PP) s_al[tid] = g_alpha[b*PP + tid];
    __syncthreads();
    int e = blockIdx.x*blockDim.x + tid;
    if (e >= ENCD) return;
    long base = ((long)g_ind[b]*PP)*ENCD + e;
    float acc = 0.f;
    #pragma unroll 4
    for (int p = 0; p < PP; p++)
        acc = fmaf(enc_out[base + (long)p*ENCD], s_al[p], acc);
    float bp = g_betapre[b*ENCD + e];
    g_awe[b*ENCD + e] = (1.f/(1.f+expf(-bp))) * acc;
}

// LSTM cell + masked state update; store h_new for all t (time-major)
__global__ void lstm_kernel(int t)
{
    int idx = blockIdx.x*blockDim.x + threadIdx.x;
    if (idx >= BB*HD) return;
    int b = idx / HD;
    long base = (long)b*G4H;
    int j = idx % HD;
    float gi = g_gates[base + j];
    float gf = g_gates[base + HD + j];
    float gg = g_gates[base + 2*HD + j];
    float go = g_gates[base + 3*HD + j];
    float si = 1.f/(1.f+expf(-gi));
    float sf = 1.f/(1.f+expf(-gf));
    float so = 1.f/(1.f+expf(-go));
    float cn = sf * g_c[idx] + si * tanhf(gg);
    float hn = so * tanhf(cn);
    g_hall[((long)t*BB + b)*HD + j] = hn;
    if (t < g_declens[b]) { g_h[idx] = hn; g_c[idx] = cn; }
}

// ---------------------------------------------------------------
extern "C" void kernel_launch(void* const* d_in, const int* in_sizes, int n_in,
                              void* d_out, int out_size)
{
    const float* enc_out  = (const float*)d_in[0];
    const int*   caps_in  = (const int*)  d_in[1];
    const int*   lengths  = (const int*)  d_in[2];
    const float* W_enc    = (const float*)d_in[3];
    const float* b_enc    = (const float*)d_in[4];
    const float* W_dec    = (const float*)d_in[5];
    const float* b_dec    = (const float*)d_in[6];
    const float* W_full   = (const float*)d_in[7];
    const float* b_full   = (const float*)d_in[8];
    const float* emb      = (const float*)d_in[9];
    const float* W_ih     = (const float*)d_in[10];
    const float* b_ih     = (const float*)d_in[11];
    const float* W_hh     = (const float*)d_in[12];
    const float* b_hh     = (const float*)d_in[13];
    const float* W_init_h = (const float*)d_in[14];
    const float* b_init_h = (const float*)d_in[15];
    const float* W_init_c = (const float*)d_in[16];
    const float* b_init_c = (const float*)d_in[17];
    const float* W_beta   = (const float*)d_in[18];
    const float* b_beta   = (const float*)d_in[19];
    const float* W_fc     = (const float*)d_in[20];
    const float* b_fc     = (const float*)d_in[21];
    float* out = (float*)d_out;

    int *p_declens, *p_rowmap;
    float *p_mean,*p_h,*p_c,*p_hall,*p_awe,*p_gates,*p_encatt,*p_embt,*p_P,*p_bihh,*p_zero;
    cudaGetSymbolAddress((void**)&p_declens, g_declens);
    cudaGetSymbolAddress((void**)&p_rowmap,  g_rowmap);
    cudaGetSymbolAddress((void**)&p_mean,    g_mean);
    cudaGetSymbolAddress((void**)&p_h,       g_h);
    cudaGetSymbolAddress((void**)&p_c,       g_c);
    cudaGetSymbolAddress((void**)&p_hall,    g_hall);
    cudaGetSymbolAddress((void**)&p_awe,     g_awe);
    cudaGetSymbolAddress((void**)&p_gates,   g_gates);
    cudaGetSymbolAddress((void**)&p_encatt,  g_encatt);
    cudaGetSymbolAddress((void**)&p_embt,    g_embt);
    cudaGetSymbolAddress((void**)&p_P,       g_P);
    cudaGetSymbolAddress((void**)&p_bihh,    g_bias_ihh);
    cudaGetSymbolAddress((void**)&p_zero,    g_zero);

    // ---------- prologue ----------
    sort_kernel<<<1, 64>>>(lengths, caps_in, out);
    rowmap_kernel<<<(BB*PP + 255)/256, 256>>>();
    bias_combine_kernel<<<G4H/256, 256>>>(b_ih, b_hh);
    embt_kernel<<<(int)(((long)MB*ED + 255)/256), 256>>>(emb);
    mean_kernel<<<dim3(ENCD/256, BB), 256>>>(enc_out);

    // h0 / c0
    sgemm<64,32,16,4,4,0>(p_mean,nullptr,ENCD, W_init_h,ENCD,b_init_h, p_h,HD, BB,HD,ENCD, nullptr);
    sgemm<64,32,16,4,4,0>(p_mean,nullptr,ENCD, W_init_c,ENCD,b_init_c, p_c,HD, BB,HD,ENCD, nullptr);

    // enc_att : (12544 x 1024) = eo @ W_enc^T   (gather via rowmap)
    sgemm<128,128,16,8,8,0>(enc_out,p_rowmap,ENCD, W_enc,ENCD,b_enc, p_encatt,AD, BB*PP,AD,ENCD, nullptr);

    // P[t] = emb_t @ W_ih[:, :512]^T + (b_ih + b_hh)   batched over all t
    sgemm<128,128,16,8,8,0>(p_embt,nullptr,ED, W_ih,XD,p_bihh, p_P,G4H, MB,G4H,ED, nullptr);

    // ---------- recurrence ----------
    for (int t = 0; t < TD; t++) {
        hgemm_kernel<<<(1024+2048+4096)/HG_BN, 128>>>(W_dec, W_beta, W_hh, b_dec, b_beta,
                                                      p_P + (long)t*BB*G4H);
        att_softmax_kernel<<<BB, 512>>>(W_full, b_full, out + O_ALPHA, t);
        ctx_awe_kernel<<<dim3(ENCD/256, BB), 256>>>(enc_out);
        // gates += awe @ W_ih[:, 512:]^T   (bias = zeros)
        sgemm<64,32,16,4,4,1>(p_awe,nullptr,ENCD, W_ih+ED,XD,p_zero, p_gates,G4H, BB,G4H,ENCD, nullptr);
        lstm_kernel<<<(BB*HD + 255)/256, 256>>>(t);
    }

    // ---------- batched predictions ----------
    sgemm<128,128,16,8,8,4>(p_hall,nullptr,HD, W_fc,HD,b_fc, out + O_PRED, VD,
                            MB, VD, HD, p_declens);
}

// round 3
// speedup vs baseline: 2.0154x; 1.6107x over previous
#include <cuda_runtime.h>
#include <cuda_bf16.h>
#include <math.h>
#include <stdint.h>

// Problem dims
#define BB   64
#define PP   196
#define ENCD 2048
#define HD   1024
#define AD   1024
#define ED   512
#define VD   10000
#define TCD  32
#define TD   31
#define XD   (ED+ENCD)
#define G4H  (4*HD)
#define MB   (TD*BB)      // 1984

// Output layout offsets (float32 elements)
#define O_PRED  0L
#define N_PRED  ((long)BB*TD*VD)
#define O_ALPHA (N_PRED)
#define N_ALPHA ((long)BB*TD*PP)
#define O_CAPS  (O_ALPHA + N_ALPHA)
#define O_DLEN  (O_CAPS + (long)BB*TCD)
#define O_IND   (O_DLEN + BB)

// -------- scratch --------
__device__ int   g_ind[BB];
__device__ int   g_declens[BB];
__device__ int   g_caps[BB*TCD];
__device__ int   g_rowmap[BB*PP];
__device__ float g_mean[BB*ENCD];
__device__ float g_h[BB*HD];
__device__ float g_c[BB*HD];
__device__ float g_hall[(long)MB*HD];
__device__ float g_dec[BB*AD];
__device__ float g_betapre[BB*ENCD];
__device__ float g_alpha[BB*PP];
__device__ float g_awe[BB*ENCD];
__device__ float g_gates[BB*G4H];
__device__ float g_embt[(long)MB*ED];
__device__ float g_P[(long)MB*G4H];
__device__ float g_bias_ihh[G4H];
__device__ float g_encatt[(long)BB*PP*AD];

__device__ __forceinline__ float to_tf32(float x) {
    uint32_t u;
    asm("cvt.rna.tf32.f32 %0, %1;" : "=r"(u) : "f"(x));
    return __uint_as_float(u);
}

__device__ __forceinline__ void mma_tf32(float* c, const uint32_t* a, const uint32_t* b) {
    asm volatile("mma.sync.aligned.m16n8k8.row.col.f32.tf32.tf32.f32 "
                 "{%0,%1,%2,%3}, {%4,%5,%6,%7}, {%8,%9}, {%0,%1,%2,%3};"
                 : "+f"(c[0]), "+f"(c[1]), "+f"(c[2]), "+f"(c[3])
                 : "r"(a[0]), "r"(a[1]), "r"(a[2]), "r"(a[3]),
                   "r"(b[0]), "r"(b[1]));
}

// ---------------------------------------------------------------
// misc small kernels
// ---------------------------------------------------------------
__global__ void sort_kernel(const int* __restrict__ lengths,
                            const int* __restrict__ caps_in,
                            float* __restrict__ out)
{
    int b = threadIdx.x;
    if (b < BB) {
        int len = lengths[b];
        int rank = 0;
        for (int b2 = 0; b2 < BB; b2++) {
            int l2 = lengths[b2];
            rank += (l2 > len) || (l2 == len && b2 < b);
        }
        g_ind[rank] = b;
    }
    __syncthreads();
    if (b < BB) {
        int i = g_ind[b];
        int dl = lengths[i] - 1;
        g_declens[b] = dl;
        out[O_DLEN + b] = (float)dl;
        out[O_IND  + b] = (float)i;
        for (int j = 0; j < TCD; j++) {
            int cv = caps_in[i*TCD + j];
            g_caps[b*TCD + j] = cv;
            out[O_CAPS + b*TCD + j] = (float)cv;
        }
    }
}

__global__ void rowmap_kernel()
{
    int m = blockIdx.x*blockDim.x + threadIdx.x;
    if (m < BB*PP) g_rowmap[m] = g_ind[m/PP]*PP + (m%PP);
}

__global__ void bias_combine_kernel(const float* __restrict__ b_ih,
                                    const float* __restrict__ b_hh)
{
    int n = blockIdx.x*blockDim.x + threadIdx.x;
    if (n < G4H) g_bias_ihh[n] = b_ih[n] + b_hh[n];
}

__global__ void embt_kernel(const float* __restrict__ emb)
{
    long idx = (long)blockIdx.x*blockDim.x + threadIdx.x;
    if (idx >= (long)MB*ED) return;
    int row = (int)(idx / ED), j = (int)(idx % ED);
    int t = row / BB, b = row % BB;
    int cap = g_caps[b*TCD + t];
    g_embt[idx] = emb[(long)cap*ED + j];
}

__global__ void mean_kernel(const float* __restrict__ enc_out)
{
    int e = blockIdx.x*blockDim.x + threadIdx.x;
    int b = blockIdx.y;
    if (e >= ENCD) return;
    long base = ((long)g_ind[b]*PP)*ENCD + e;
    float acc = 0.f;
    for (int p = 0; p < PP; p++) acc += enc_out[base + (long)p*ENCD];
    g_mean[b*ENCD + e] = acc / (float)PP;
}

// ---------------------------------------------------------------
// TF32 tensor-core GEMM:  C = A(MxK) @ W(NxK)^T (+bias)
//  EPI 0: write C[m,n] = v + bias
//  EPI 1: accumulate C[m,n] += v        (no bias)
//  EPI 4: preds scatter: out[(b*TD+t)*ldc+n] = (v+bias)*mask, m = t*BB+b
// Warp computes 32x32 via m16n8k8 mma. BM in {64,128}, BN=64, BK=32.
// M must be a multiple of BM; N is guarded.
// ---------------------------------------------------------------
template<int BM,int BN,int BK,int EPI>
__global__ __launch_bounds__((BM/32)*(BN/32)*32)
void mma_gemm_kernel(const float* __restrict__ A, const int* __restrict__ rowmap, int lda,
                     const float* __restrict__ W, int ldw,
                     const float* __restrict__ bias,
                     float* __restrict__ C, int ldc,
                     int M, int N, int K,
                     const int* __restrict__ declens)
{
    constexpr int WR = BM/32, WC = BN/32;
    constexpr int NT = WR*WC*32;
    constexpr int LD = BK+4;
    __shared__ float As[BM*LD];
    __shared__ float Bs[BN*LD];

    const int tid = threadIdx.x;
    const int m0 = blockIdx.y*BM, n0 = blockIdx.x*BN;
    const int warp = tid >> 5, lane = tid & 31;
    const int wm = (warp % WR)*32, wn = (warp / WR)*32;
    const int g = lane >> 2, tg = lane & 3;

    float acc[2][4][4];
    #pragma unroll
    for (int i=0;i<2;i++)
        #pragma unroll
        for (int j=0;j<4;j++)
            #pragma unroll
            for (int q=0;q<4;q++) acc[i][j][q]=0.f;

    for (int k0 = 0; k0 < K; k0 += BK) {
        #pragma unroll
        for (int s = tid; s < BM*(BK/4); s += NT) {
            int r  = s / (BK/4);
            int kk = (s % (BK/4))*4;
            long src = rowmap ? ((long)rowmap[m0+r]*lda) : ((long)(m0+r)*lda);
            float4 v = *reinterpret_cast<const float4*>(A + src + k0 + kk);
            float* dst = &As[r*LD + kk];
            dst[0]=to_tf32(v.x); dst[1]=to_tf32(v.y);
            dst[2]=to_tf32(v.z); dst[3]=to_tf32(v.w);
        }
        #pragma unroll
        for (int s = tid; s < BN*(BK/4); s += NT) {
            int r  = s / (BK/4);
            int kk = (s % (BK/4))*4;
            int n = n0 + r;
            float4 v = make_float4(0.f,0.f,0.f,0.f);
            if (n < N) v = *reinterpret_cast<const float4*>(W + (long)n*ldw + k0 + kk);
            float* dst = &Bs[r*LD + kk];
            dst[0]=to_tf32(v.x); dst[1]=to_tf32(v.y);
            dst[2]=to_tf32(v.z); dst[3]=to_tf32(v.w);
        }
        __syncthreads();
        #pragma unroll
        for (int kk = 0; kk < BK; kk += 8) {
            uint32_t af[2][4], bf[4][2];
            #pragma unroll
            for (int i=0;i<2;i++) {
                int rb = (wm + i*16 + g)*LD + kk + tg;
                af[i][0] = __float_as_uint(As[rb]);
                af[i][1] = __float_as_uint(As[rb + 8*LD]);
                af[i][2] = __float_as_uint(As[rb + 4]);
                af[i][3] = __float_as_uint(As[rb + 8*LD + 4]);
            }
            #pragma unroll
            for (int j=0;j<4;j++) {
                int rb = (wn + j*8 + g)*LD + kk + tg;
                bf[j][0] = __float_as_uint(Bs[rb]);
                bf[j][1] = __float_as_uint(Bs[rb + 4]);
            }
            #pragma unroll
            for (int i=0;i<2;i++)
                #pragma unroll
                for (int j=0;j<4;j++)
                    mma_tf32(acc[i][j], af[i], bf[j]);
        }
        __syncthreads();
    }

    #pragma unroll
    for (int i=0;i<2;i++) {
        #pragma unroll
        for (int ci=0;ci<2;ci++) {
            int m = m0 + wm + i*16 + g + ci*8;
            float mf = 1.f; long orow = 0;
            if (EPI == 4) {
                int tt = m / BB, bb = m % BB;
                mf = (tt < declens[bb]) ? 1.f : 0.f;
                orow = (long)bb*TD + tt;
            }
            #pragma unroll
            for (int j=0;j<4;j++) {
                #pragma unroll
                for (int cj=0;cj<2;cj++) {
                    int n = n0 + wn + j*8 + 2*tg + cj;
                    if (n >= N) continue;
                    float v = acc[i][j][ci*2+cj];
                    if      (EPI == 0) C[(long)m*ldc + n] = v + bias[n];
                    else if (EPI == 1) C[(long)m*ldc + n] += v;
                    else               C[orow*ldc + n] = (v + bias[n]) * mf;
                }
            }
        }
    }
}

template<int BM,int BN,int BK,int EPI>
static inline void mma_gemm(const float*A,const int*rowmap,int lda,
                            const float*W,int ldw,const float*bias,
                            float*C,int ldc,int M,int N,int K,
                            const int*declens)
{
    dim3 grid((N+BN-1)/BN, M/BM);
    mma_gemm_kernel<BM,BN,BK,EPI><<<grid,(BM/32)*(BN/32)*32>>>(
        A,rowmap,lda,W,ldw,bias,C,ldc,M,N,K,declens);
}

// ---------------------------------------------------------------
// Fused per-step h-GEMM (tensor core): A = g_h (64x1024),
// weights concat along N: [W_dec(1024) | W_beta(2048) | W_hh(4096)]
//   n<1024:        g_dec     = v + b_dec
//   1024<=n<3072:  g_betapre = v + b_beta
//   n>=3072:       g_gates   = v + Pt          (b_ih+b_hh folded into Pt)
// BM=64, BN=64, BK=32, 128 threads, grid 112.
// ---------------------------------------------------------------
__global__ __launch_bounds__(128)
void mma_hgemm_kernel(const float* __restrict__ Wdec,
                      const float* __restrict__ Wbeta,
                      const float* __restrict__ Whh,
                      const float* __restrict__ bdec,
                      const float* __restrict__ bbeta,
                      const float* __restrict__ Pt)
{
    constexpr int BM=64, BN=64, BK=32, LD=BK+4, NT=128;
    __shared__ float As[BM*LD];
    __shared__ float Bs[BN*LD];

    const int tid = threadIdx.x;
    const int n0 = blockIdx.x*BN;
    const int warp = tid >> 5, lane = tid & 31;
    const int wm = (warp % 2)*32, wn = (warp / 2)*32;
    const int g = lane >> 2, tg = lane & 3;

    float acc[2][4][4];
    #pragma unroll
    for (int i=0;i<2;i++)
        #pragma unroll
        for (int j=0;j<4;j++)
            #pragma unroll
            for (int q=0;q<4;q++) acc[i][j][q]=0.f;

    for (int k0 = 0; k0 < HD; k0 += BK) {
        #pragma unroll
        for (int s = tid; s < BM*(BK/4); s += NT) {
            int r  = s / (BK/4);
            int kk = (s % (BK/4))*4;
            float4 v = *reinterpret_cast<const float4*>(g_h + (long)r*HD + k0 + kk);
            float* dst = &As[r*LD + kk];
            dst[0]=to_tf32(v.x); dst[1]=to_tf32(v.y);
            dst[2]=to_tf32(v.z); dst[3]=to_tf32(v.w);
        }
        #pragma unroll
        for (int s = tid; s < BN*(BK/4); s += NT) {
            int r  = s / (BK/4);
            int kk = (s % (BK/4))*4;
            int gn = n0 + r;
            const float* wrow;
            if (gn < 1024)      wrow = Wdec  + (long)gn*HD;
            else if (gn < 3072) wrow = Wbeta + (long)(gn-1024)*HD;
            else                wrow = Whh   + (long)(gn-3072)*HD;
            float4 v = *reinterpret_cast<const float4*>(wrow + k0 + kk);
            float* dst = &Bs[r*LD + kk];
            dst[0]=to_tf32(v.x); dst[1]=to_tf32(v.y);
            dst[2]=to_tf32(v.z); dst[3]=to_tf32(v.w);
        }
        __syncthreads();
        #pragma unroll
        for (int kk = 0; kk < BK; kk += 8) {
            uint32_t af[2][4], bf[4][2];
            #pragma unroll
            for (int i=0;i<2;i++) {
                int rb = (wm + i*16 + g)*LD + kk + tg;
                af[i][0] = __float_as_uint(As[rb]);
                af[i][1] = __float_as_uint(As[rb + 8*LD]);
                af[i][2] = __float_as_uint(As[rb + 4]);
                af[i][3] = __float_as_uint(As[rb + 8*LD + 4]);
            }
            #pragma unroll
            for (int j=0;j<4;j++) {
                int rb = (wn + j*8 + g)*LD + kk + tg;
                bf[j][0] = __float_as_uint(Bs[rb]);
                bf[j][1] = __float_as_uint(Bs[rb + 4]);
            }
            #pragma unroll
            for (int i=0;i<2;i++)
                #pragma unroll
                for (int j=0;j<4;j++)
                    mma_tf32(acc[i][j], af[i], bf[j]);
        }
        __syncthreads();
    }

    #pragma unroll
    for (int i=0;i<2;i++) {
        #pragma unroll
        for (int ci=0;ci<2;ci++) {
            int m = wm + i*16 + g + ci*8;
            #pragma unroll
            for (int j=0;j<4;j++) {
                #pragma unroll
                for (int cj=0;cj<2;cj++) {
                    int n = n0 + wn + j*8 + 2*tg + cj;
                    float v = acc[i][j][ci*2+cj];
                    if (n < 1024)      g_dec[m*AD + n]              = v + bdec[n];
                    else if (n < 3072) g_betapre[m*ENCD + (n-1024)] = v + bbeta[n-1024];
                    else {
                        int nn = n - 3072;
                        g_gates[m*G4H + nn] = v + Pt[(long)m*G4H + nn];
                    }
                }
            }
        }
    }
}

// ---------------------------------------------------------------
// Fused attention scores + softmax (one block / batch row)
// ---------------------------------------------------------------
__global__ __launch_bounds__(512)
void att_softmax_kernel(const float* __restrict__ wfull,
                        const float* __restrict__ bfull,
                        float* __restrict__ out_alphas, int t)
{
    __shared__ float s_dec[AD];
    __shared__ float s_wf[AD];
    __shared__ float s_sc[PP];
    __shared__ float s_red[16];

    const int b = blockIdx.x;
    const int tid = threadIdx.x;
    const int warp = tid >> 5, lane = tid & 31;

    for (int i = tid; i < AD; i += 512) {
        s_dec[i] = g_dec[b*AD + i];
        s_wf[i]  = wfull[i];
    }
    __syncthreads();

    const float bf = bfull[0];
    for (int p = warp; p < PP; p += 16) {
        const float* row = g_encatt + ((long)b*PP + p)*AD;
        float acc = 0.f;
        for (int a = lane; a < AD; a += 32) {
            float v = row[a] + s_dec[a];
            v = v > 0.f ? v : 0.f;
            acc = fmaf(v, s_wf[a], acc);
        }
        #pragma unroll
        for (int o = 16; o > 0; o >>= 1) acc += __shfl_down_sync(0xffffffffu, acc, o);
        if (lane == 0) s_sc[p] = acc + bf;
    }
    __syncthreads();

    float v = (tid < PP) ? s_sc[tid] : -INFINITY;
    float m = v;
    #pragma unroll
    for (int o = 16; o > 0; o >>= 1) m = fmaxf(m, __shfl_xor_sync(0xffffffffu, m, o));
    if (lane == 0) s_red[warp] = m;
    __syncthreads();
    if (warp == 0) {
        float mm = (lane < 16) ? s_red[lane] : -INFINITY;
        #pragma unroll
        for (int o = 8; o > 0; o >>= 1) mm = fmaxf(mm, __shfl_xor_sync(0xffffffffu, mm, o));
        if (lane == 0) s_red[0] = mm;
    }
    __syncthreads();
    const float bmax = s_red[0];
    float e = (tid < PP) ? expf(v - bmax) : 0.f;
    float s = e;
    #pragma unroll
    for (int o = 16; o > 0; o >>= 1) s += __shfl_xor_sync(0xffffffffu, s, o);
    __syncthreads();
    if (lane == 0) s_red[warp] = s;
    __syncthreads();
    if (warp == 0) {
        float ss = (lane < 16) ? s_red[lane] : 0.f;
        #pragma unroll
        for (int o = 8; o > 0; o >>= 1) ss += __shfl_xor_sync(0xffffffffu, ss, o);
        if (lane == 0) s_red[0] = ss;
    }
    __syncthreads();
    const float inv = 1.f / s_red[0];
    if (tid < PP) {
        float al = e * inv;
        g_alpha[b*PP + tid] = al;
        float mf = (t < g_declens[b]) ? 1.f : 0.f;
        out_alphas[((long)b*TD + t)*PP + tid] = al * mf;
    }
}

// context + fused awe: awe[b,e] = sigmoid(betapre[b,e]) * sum_p eo*alpha
__global__ void ctx_awe_kernel(const float* __restrict__ enc_out)
{
    __shared__ float s_al[PP];
    const int b = blockIdx.y;
    const int tid = threadIdx.x;
    if (tid < PP) s_al[tid] = g_alpha[b*PP + tid];
    __syncthreads();
    int e = blockIdx.x*blockDim.x + tid;
    if (e >= ENCD) return;
    long base = ((long)g_ind[b]*PP)*ENCD + e;
    float acc = 0.f;
    #pragma unroll 4
    for (int p = 0; p < PP; p++)
        acc = fmaf(enc_out[base + (long)p*ENCD], s_al[p], acc);
    float bp = g_betapre[b*ENCD + e];
    g_awe[b*ENCD + e] = (1.f/(1.f+expf(-bp))) * acc;
}

// LSTM cell + masked state update; store h_new for all t (time-major)
__global__ void lstm_kernel(int t)
{
    int idx = blockIdx.x*blockDim.x + threadIdx.x;
    if (idx >= BB*HD) return;
    int b = idx / HD;
    long base = (long)b*G4H;
    int j = idx % HD;
    float gi = g_gates[base + j];
    float gf = g_gates[base + HD + j];
    float gg = g_gates[base + 2*HD + j];
    float go = g_gates[base + 3*HD + j];
    float si = 1.f/(1.f+expf(-gi));
    float sf = 1.f/(1.f+expf(-gf));
    float so = 1.f/(1.f+expf(-go));
    float cn = sf * g_c[idx] + si * tanhf(gg);
    float hn = so * tanhf(cn);
    g_hall[((long)t*BB + b)*HD + j] = hn;
    if (t < g_declens[b]) { g_h[idx] = hn; g_c[idx] = cn; }
}

// ---------------------------------------------------------------
extern "C" void kernel_launch(void* const* d_in, const int* in_sizes, int n_in,
                              void* d_out, int out_size)
{
    const float* enc_out  = (const float*)d_in[0];
    const int*   caps_in  = (const int*)  d_in[1];
    const int*   lengths  = (const int*)  d_in[2];
    const float* W_enc    = (const float*)d_in[3];
    const float* b_enc    = (const float*)d_in[4];
    const float* W_dec    = (const float*)d_in[5];
    const float* b_dec    = (const float*)d_in[6];
    const float* W_full   = (const float*)d_in[7];
    const float* b_full   = (const float*)d_in[8];
    const float* emb      = (const float*)d_in[9];
    const float* W_ih     = (const float*)d_in[10];
    const float* b_ih     = (const float*)d_in[11];
    const float* W_hh     = (const float*)d_in[12];
    const float* b_hh     = (const float*)d_in[13];
    const float* W_init_h = (const float*)d_in[14];
    const float* b_init_h = (const float*)d_in[15];
    const float* W_init_c = (const float*)d_in[16];
    const float* b_init_c = (const float*)d_in[17];
    const float* W_beta   = (const float*)d_in[18];
    const float* b_beta   = (const float*)d_in[19];
    const float* W_fc     = (const float*)d_in[20];
    const float* b_fc     = (const float*)d_in[21];
    float* out = (float*)d_out;

    int *p_declens, *p_rowmap;
    float *p_mean,*p_h,*p_c,*p_hall,*p_awe,*p_gates,*p_encatt,*p_embt,*p_P,*p_bihh;
    cudaGetSymbolAddress((void**)&p_declens, g_declens);
    cudaGetSymbolAddress((void**)&p_rowmap,  g_rowmap);
    cudaGetSymbolAddress((void**)&p_mean,    g_mean);
    cudaGetSymbolAddress((void**)&p_h,       g_h);
    cudaGetSymbolAddress((void**)&p_c,       g_c);
    cudaGetSymbolAddress((void**)&p_hall,    g_hall);
    cudaGetSymbolAddress((void**)&p_awe,     g_awe);
    cudaGetSymbolAddress((void**)&p_gates,   g_gates);
    cudaGetSymbolAddress((void**)&p_encatt,  g_encatt);
    cudaGetSymbolAddress((void**)&p_embt,    g_embt);
    cudaGetSymbolAddress((void**)&p_P,       g_P);
    cudaGetSymbolAddress((void**)&p_bihh,    g_bias_ihh);

    // ---------- prologue ----------
    sort_kernel<<<1, 64>>>(lengths, caps_in, out);
    rowmap_kernel<<<(BB*PP + 255)/256, 256>>>();
    bias_combine_kernel<<<G4H/256, 256>>>(b_ih, b_hh);
    embt_kernel<<<(int)(((long)MB*ED + 255)/256), 256>>>(emb);
    mean_kernel<<<dim3(ENCD/256, BB), 256>>>(enc_out);

    // h0 / c0 : (64 x 1024), K=2048
    mma_gemm<64,64,32,0>(p_mean,nullptr,ENCD, W_init_h,ENCD,b_init_h, p_h,HD, BB,HD,ENCD, nullptr);
    mma_gemm<64,64,32,0>(p_mean,nullptr,ENCD, W_init_c,ENCD,b_init_c, p_c,HD, BB,HD,ENCD, nullptr);

    // enc_att : (12544 x 1024), K=2048 (gather via rowmap)
    mma_gemm<128,64,32,0>(enc_out,p_rowmap,ENCD, W_enc,ENCD,b_enc, p_encatt,AD, BB*PP,AD,ENCD, nullptr);

    // P = embt @ W_ih[:, :512]^T + (b_ih+b_hh) : (1984 x 4096), K=512
    mma_gemm<64,64,32,0>(p_embt,nullptr,ED, W_ih,XD,p_bihh, p_P,G4H, MB,G4H,ED, nullptr);

    // ---------- recurrence ----------
    for (int t = 0; t < TD; t++) {
        mma_hgemm_kernel<<<(1024+2048+4096)/64, 128>>>(W_dec, W_beta, W_hh, b_dec, b_beta,
                                                       p_P + (long)t*BB*G4H);
        att_softmax_kernel<<<BB, 512>>>(W_full, b_full, out + O_ALPHA, t);
        ctx_awe_kernel<<<dim3(ENCD/256, BB), 256>>>(enc_out);
        // gates += awe @ W_ih[:, 512:]^T : (64 x 4096), K=2048
        mma_gemm<64,64,32,1>(p_awe,nullptr,ENCD, W_ih+ED,XD,nullptr, p_gates,G4H, BB,G4H,ENCD, nullptr);
        lstm_kernel<<<(BB*HD + 255)/256, 256>>>(t);
    }

    // ---------- batched predictions : (1984 x 10000), K=1024 ----------
    mma_gemm<64,64,32,4>(p_hall,nullptr,HD, W_fc,HD,b_fc, out + O_PRED, VD,
                         MB, VD, HD, p_declens);
}

// round 5
// speedup vs baseline: 3.9482x; 1.9591x over previous
#include <cuda_runtime.h>
#include <cuda_fp16.h>
#include <math.h>
#include <stdint.h>

// Problem dims
#define BB   64
#define PP   196
#define ENCD 2048
#define HD   1024
#define AD   1024
#define ED   512
#define VD   10000
#define TCD  32
#define TD   31
#define XD   (ED+ENCD)
#define G4H  (4*HD)
#define MB   (TD*BB)      // 1984
#define KSPL 4            // K-split factor for awe gemm
#define KCH  (ENCD/KSPL)  // 512

// Output layout offsets (float32 elements)
#define O_PRED  0L
#define N_PRED  ((long)BB*TD*VD)
#define O_ALPHA (N_PRED)
#define N_ALPHA ((long)BB*TD*PP)
#define O_CAPS  (O_ALPHA + N_ALPHA)
#define O_DLEN  (O_CAPS + (long)BB*TCD)
#define O_IND   (O_DLEN + BB)

// -------- scratch --------
__device__ int    g_ind[BB];
__device__ int    g_declens[BB];
__device__ int    g_caps[BB*TCD];
__device__ int    g_rowmap[BB*PP];
__device__ float  g_mean[BB*ENCD];
__device__ float  g_h[BB*HD];
__device__ float  g_c[BB*HD];
__device__ float  g_hall[(long)MB*HD];
__device__ float  g_decpart[2*BB*AD];
__device__ float  g_betapart[2*BB*ENCD];
__device__ float  g_score[BB*PP];
__device__ float  g_alpha[BB*PP];
__device__ float  g_awe[BB*ENCD];
__device__ float  g_gpart[6*BB*G4H];          // 0..3 awe K-split, 4..5 hh K-split
__device__ float  g_embt[(long)MB*ED];
__device__ float  g_P[(long)MB*G4H];
__device__ float  g_bias_ihh[G4H];
__device__ __half g_encatt_hf[(long)BB*PP*AD];   // 25.7 MB
__device__ __half g_eohf[(long)BB*PP*ENCD];      // 51.4 MB (sorted order)

__device__ __forceinline__ float to_tf32(float x) {
    uint32_t u;
    asm("cvt.rna.tf32.f32 %0, %1;" : "=r"(u) : "f"(x));
    return __uint_as_float(u);
}

__device__ __forceinline__ void mma_tf32(float* c, const uint32_t* a, const uint32_t* b) {
    asm volatile("mma.sync.aligned.m16n8k8.row.col.f32.tf32.tf32.f32 "
                 "{%0,%1,%2,%3}, {%4,%5,%6,%7}, {%8,%9}, {%0,%1,%2,%3};"
                 : "+f"(c[0]), "+f"(c[1]), "+f"(c[2]), "+f"(c[3])
                 : "r"(a[0]), "r"(a[1]), "r"(a[2]), "r"(a[3]),
                   "r"(b[0]), "r"(b[1]));
}

// ---------------------------------------------------------------
// misc small kernels
// ---------------------------------------------------------------
__global__ void sort_kernel(const int* __restrict__ lengths,
                            const int* __restrict__ caps_in,
                            float* __restrict__ out)
{
    int b = threadIdx.x;
    if (b < BB) {
        int len = lengths[b];
        int rank = 0;
        for (int b2 = 0; b2 < BB; b2++) {
            int l2 = lengths[b2];
            rank += (l2 > len) || (l2 == len && b2 < b);
        }
        g_ind[rank] = b;
    }
    __syncthreads();
    if (b < BB) {
        int i = g_ind[b];
        int dl = lengths[i] - 1;
        g_declens[b] = dl;
        out[O_DLEN + b] = (float)dl;
        out[O_IND  + b] = (float)i;
        for (int j = 0; j < TCD; j++) {
            int cv = caps_in[i*TCD + j];
            g_caps[b*TCD + j] = cv;
            out[O_CAPS + b*TCD + j] = (float)cv;
        }
    }
}

__global__ void rowmap_kernel()
{
    int m = blockIdx.x*blockDim.x + threadIdx.x;
    if (m < BB*PP) g_rowmap[m] = g_ind[m/PP]*PP + (m%PP);
}

__global__ void bias_combine_kernel(const float* __restrict__ b_ih,
                                    const float* __restrict__ b_hh)
{
    int n = blockIdx.x*blockDim.x + threadIdx.x;
    if (n < G4H) g_bias_ihh[n] = b_ih[n] + b_hh[n];
}

__global__ void embt_kernel(const float* __restrict__ emb)
{
    long idx = (long)blockIdx.x*blockDim.x + threadIdx.x;
    if (idx >= (long)MB*ED) return;
    int row = (int)(idx / ED), j = (int)(idx % ED);
    int t = row / BB, b = row % BB;
    int cap = g_caps[b*TCD + t];
    g_embt[idx] = emb[(long)cap*ED + j];
}

__global__ void mean_kernel(const float* __restrict__ enc_out)
{
    int e = blockIdx.x*blockDim.x + threadIdx.x;
    int b = blockIdx.y;
    if (e >= ENCD) return;
    long base = ((long)g_ind[b]*PP)*ENCD + e;
    float acc = 0.f;
    for (int p = 0; p < PP; p++) acc += enc_out[base + (long)p*ENCD];
    g_mean[b*ENCD + e] = acc / (float)PP;
}

// convert sorted eo to fp16
__global__ void eohf_kernel(const float* __restrict__ enc_out)
{
    long idx4 = ((long)blockIdx.x*blockDim.x + threadIdx.x);
    if (idx4 >= (long)BB*PP*ENCD/4) return;
    long idx = idx4*4;
    int b = (int)(idx / ((long)PP*ENCD));
    long rem = idx - (long)b*PP*ENCD;
    const float4 v = *reinterpret_cast<const float4*>(enc_out + (long)g_ind[b]*PP*ENCD + rem);
    __half2 o0 = __floats2half2_rn(v.x, v.y);
    __half2 o1 = __floats2half2_rn(v.z, v.w);
    *reinterpret_cast<__half2*>(g_eohf + idx)     = o0;
    *reinterpret_cast<__half2*>(g_eohf + idx + 2) = o1;
}

// ---------------------------------------------------------------
// TF32 64x64 GEMM (4 warps):
//  EPI 0: C[m,n] = v + bias
//  EPI 6: K-split partial: C[z*M*ldc + m*ldc + n] = v
// ---------------------------------------------------------------
template<int EPI>
__global__ __launch_bounds__(128)
void mma_gemm64_kernel(const float* __restrict__ A, int lda,
                       const float* __restrict__ W, int ldw,
                       const float* __restrict__ bias,
                       float* __restrict__ C, int ldc,
                       int M, int N, int K)
{
    constexpr int BM=64, BN=64, BK=32, LD=BK+4, NT=128;
    __shared__ float As[BM*LD];
    __shared__ float Bs[BN*LD];

    const int tid = threadIdx.x;
    const int m0 = blockIdx.y*BM, n0 = blockIdx.x*BN;
    const long kbase = (long)blockIdx.z * K;
    const int warp = tid >> 5, lane = tid & 31;
    const int wm = (warp % 2)*32, wn = (warp / 2)*32;
    const int g = lane >> 2, tg = lane & 3;

    float acc[2][4][4];
    #pragma unroll
    for (int i=0;i<2;i++)
        #pragma unroll
        for (int j=0;j<4;j++)
            #pragma unroll
            for (int q=0;q<4;q++) acc[i][j][q]=0.f;

    for (int k0 = 0; k0 < K; k0 += BK) {
        #pragma unroll
        for (int s = tid; s < BM*(BK/4); s += NT) {
            int r  = s / (BK/4);
            int kk = (s % (BK/4))*4;
            int row = m0 + r;
            float4 v = make_float4(0.f,0.f,0.f,0.f);
            if (row < M) v = *reinterpret_cast<const float4*>(A + (long)row*lda + kbase + k0 + kk);
            float* dst = &As[r*LD + kk];
            dst[0]=to_tf32(v.x); dst[1]=to_tf32(v.y);
            dst[2]=to_tf32(v.z); dst[3]=to_tf32(v.w);
        }
        #pragma unroll
        for (int s = tid; s < BN*(BK/4); s += NT) {
            int r  = s / (BK/4);
            int kk = (s % (BK/4))*4;
            int n = n0 + r;
            float4 v = make_float4(0.f,0.f,0.f,0.f);
            if (n < N) v = *reinterpret_cast<const float4*>(W + (long)n*ldw + kbase + k0 + kk);
            float* dst = &Bs[r*LD + kk];
            dst[0]=to_tf32(v.x); dst[1]=to_tf32(v.y);
            dst[2]=to_tf32(v.z); dst[3]=to_tf32(v.w);
        }
        __syncthreads();
        #pragma unroll
        for (int kk = 0; kk < BK; kk += 8) {
            uint32_t af[2][4], bf[4][2];
            #pragma unroll
            for (int i=0;i<2;i++) {
                int rb = (wm + i*16 + g)*LD + kk + tg;
                af[i][0] = __float_as_uint(As[rb]);
                af[i][1] = __float_as_uint(As[rb + 8*LD]);
                af[i][2] = __float_as_uint(As[rb + 4]);
                af[i][3] = __float_as_uint(As[rb + 8*LD + 4]);
            }
            #pragma unroll
            for (int j=0;j<4;j++) {
                int rb = (wn + j*8 + g)*LD + kk + tg;
                bf[j][0] = __float_as_uint(Bs[rb]);
                bf[j][1] = __float_as_uint(Bs[rb + 4]);
            }
            #pragma unroll
            for (int i=0;i<2;i++)
                #pragma unroll
                for (int j=0;j<4;j++)
                    mma_tf32(acc[i][j], af[i], bf[j]);
        }
        __syncthreads();
    }

    const long zoff = (EPI == 6) ? (long)blockIdx.z * M * ldc : 0;
    #pragma unroll
    for (int i=0;i<2;i++) {
        #pragma unroll
        for (int ci=0;ci<2;ci++) {
            int m = m0 + wm + i*16 + g + ci*8;
            if (m >= M) continue;
            #pragma unroll
            for (int j=0;j<4;j++) {
                #pragma unroll
                for (int cj=0;cj<2;cj++) {
                    int n = n0 + wn + j*8 + 2*tg + cj;
                    if (n >= N) continue;
                    float v = acc[i][j][ci*2+cj];
                    if (EPI == 0) C[(long)m*ldc + n] = v + bias[n];
                    else          C[zoff + (long)m*ldc + n] = v;
                }
            }
        }
    }
}

// ---------------------------------------------------------------
// TF32 128x128 GEMM (8 warps, warp tile 32x64):
//  EPI 0: fp32 write + bias
//  EPI 4: preds scatter (m=t*BB+b -> row b*TD+t) * mask
//  EPI 5: fp16 write + bias (encatt)
// ---------------------------------------------------------------
template<int EPI>
__global__ __launch_bounds__(256)
void mma_gemm128_kernel(const float* __restrict__ A, const int* __restrict__ rowmap, int lda,
                        const float* __restrict__ W, int ldw,
                        const float* __restrict__ bias,
                        void* __restrict__ Cv, int ldc,
                        int M, int N, int K,
                        const int* __restrict__ declens)
{
    constexpr int BM=128, BN=128, BK=32, LD=BK+4, NT=256;
    __shared__ float As[BM*LD];
    __shared__ float Bs[BN*LD];

    const int tid = threadIdx.x;
    const int m0 = blockIdx.y*BM, n0 = blockIdx.x*BN;
    const int warp = tid >> 5, lane = tid & 31;
    const int wm = (warp % 4)*32, wn = (warp / 4)*64;
    const int g = lane >> 2, tg = lane & 3;

    float acc[2][8][4];
    #pragma unroll
    for (int i=0;i<2;i++)
        #pragma unroll
        for (int j=0;j<8;j++)
            #pragma unroll
            for (int q=0;q<4;q++) acc[i][j][q]=0.f;

    for (int k0 = 0; k0 < K; k0 += BK) {
        #pragma unroll
        for (int s = tid; s < BM*(BK/4); s += NT) {
            int r  = s / (BK/4);
            int kk = (s % (BK/4))*4;
            int row = m0 + r;
            float4 v = make_float4(0.f,0.f,0.f,0.f);
            if (row < M) {
                long src = rowmap ? ((long)rowmap[row]*lda) : ((long)row*lda);
                v = *reinterpret_cast<const float4*>(A + src + k0 + kk);
            }
            float* dst = &As[r*LD + kk];
            dst[0]=to_tf32(v.x); dst[1]=to_tf32(v.y);
            dst[2]=to_tf32(v.z); dst[3]=to_tf32(v.w);
        }
        #pragma unroll
        for (int s = tid; s < BN*(BK/4); s += NT) {
            int r  = s / (BK/4);
            int kk = (s % (BK/4))*4;
            int n = n0 + r;
            float4 v = make_float4(0.f,0.f,0.f,0.f);
            if (n < N) v = *reinterpret_cast<const float4*>(W + (long)n*ldw + k0 + kk);
            float* dst = &Bs[r*LD + kk];
            dst[0]=to_tf32(v.x); dst[1]=to_tf32(v.y);
            dst[2]=to_tf32(v.z); dst[3]=to_tf32(v.w);
        }
        __syncthreads();
        #pragma unroll
        for (int kk = 0; kk < BK; kk += 8) {
            uint32_t af[2][4], bf[8][2];
            #pragma unroll
            for (int i=0;i<2;i++) {
                int rb = (wm + i*16 + g)*LD + kk + tg;
                af[i][0] = __float_as_uint(As[rb]);
                af[i][1] = __float_as_uint(As[rb + 8*LD]);
                af[i][2] = __float_as_uint(As[rb + 4]);
                af[i][3] = __float_as_uint(As[rb + 8*LD + 4]);
            }
            #pragma unroll
            for (int j=0;j<8;j++) {
                int rb = (wn + j*8 + g)*LD + kk + tg;
                bf[j][0] = __float_as_uint(Bs[rb]);
                bf[j][1] = __float_as_uint(Bs[rb + 4]);
            }
            #pragma unroll
            for (int i=0;i<2;i++)
                #pragma unroll
                for (int j=0;j<8;j++)
                    mma_tf32(acc[i][j], af[i], bf[j]);
        }
        __syncthreads();
    }

    float* Cf = (float*)Cv;
    __half* Ch = (__half*)Cv;
    #pragma unroll
    for (int i=0;i<2;i++) {
        #pragma unroll
        for (int ci=0;ci<2;ci++) {
            int m = m0 + wm + i*16 + g + ci*8;
            if (m >= M) continue;
            float mf = 1.f; long orow = (long)m;
            if (EPI == 4) {
                int tt = m / BB, bb = m % BB;
                mf = (tt < declens[bb]) ? 1.f : 0.f;
                orow = (long)bb*TD + tt;
            }
            #pragma unroll
            for (int j=0;j<8;j++) {
                #pragma unroll
                for (int cj=0;cj<2;cj++) {
                    int n = n0 + wn + j*8 + 2*tg + cj;
                    if (n >= N) continue;
                    float v = acc[i][j][ci*2+cj] + bias[n];
                    if      (EPI == 0) Cf[(long)m*ldc + n] = v;
                    else if (EPI == 4) Cf[orow*ldc + n] = v * mf;
                    else               Ch[(long)m*ldc + n] = __float2half(v);
                }
            }
        }
    }
}

// ---------------------------------------------------------------
// Per-step h-GEMM, K-split (grid.z in {0,1}, K-chunk 512):
// weights concat along N: [W_dec(1024) | W_beta(2048) | W_hh(4096)]
// writes raw partials; consumers merge + add bias.
// ---------------------------------------------------------------
__global__ __launch_bounds__(128)
void mma_hgemm_kernel(const float* __restrict__ Wdec,
                      const float* __restrict__ Wbeta,
                      const float* __restrict__ Whh)
{
    constexpr int BM=64, BN=64, BK=32, LD=BK+4, NT=128, KC=HD/2;
    __shared__ float As[BM*LD];
    __shared__ float Bs[BN*LD];

    const int tid = threadIdx.x;
    const int n0 = blockIdx.x*BN;
    const int z = blockIdx.z;
    const long kbase = (long)z*KC;
    const int warp = tid >> 5, lane = tid & 31;
    const int wm = (warp % 2)*32, wn = (warp / 2)*32;
    const int g = lane >> 2, tg = lane & 3;

    float acc[2][4][4];
    #pragma unroll
    for (int i=0;i<2;i++)
        #pragma unroll
        for (int j=0;j<4;j++)
            #pragma unroll
            for (int q=0;q<4;q++) acc[i][j][q]=0.f;

    for (int k0 = 0; k0 < KC; k0 += BK) {
        #pragma unroll
        for (int s = tid; s < BM*(BK/4); s += NT) {
            int r  = s / (BK/4);
            int kk = (s % (BK/4))*4;
            float4 v = *reinterpret_cast<const float4*>(g_h + (long)r*HD + kbase + k0 + kk);
            float* dst = &As[r*LD + kk];
            dst[0]=to_tf32(v.x); dst[1]=to_tf32(v.y);
            dst[2]=to_tf32(v.z); dst[3]=to_tf32(v.w);
        }
        #pragma unroll
        for (int s = tid; s < BN*(BK/4); s += NT) {
            int r  = s / (BK/4);
            int kk = (s % (BK/4))*4;
            int gn = n0 + r;
            const float* wrow;
            if (gn < 1024)      wrow = Wdec  + (long)gn*HD;
            else if (gn < 3072) wrow = Wbeta + (long)(gn-1024)*HD;
            else                wrow = Whh   + (long)(gn-3072)*HD;
            float4 v = *reinterpret_cast<const float4*>(wrow + kbase + k0 + kk);
            float* dst = &Bs[r*LD + kk];
            dst[0]=to_tf32(v.x); dst[1]=to_tf32(v.y);
            dst[2]=to_tf32(v.z); dst[3]=to_tf32(v.w);
        }
        __syncthreads();
        #pragma unroll
        for (int kk = 0; kk < BK; kk += 8) {
            uint32_t af[2][4], bf[4][2];
            #pragma unroll
            for (int i=0;i<2;i++) {
                int rb = (wm + i*16 + g)*LD + kk + tg;
                af[i][0] = __float_as_uint(As[rb]);
                af[i][1] = __float_as_uint(As[rb + 8*LD]);
                af[i][2] = __float_as_uint(As[rb + 4]);
                af[i][3] = __float_as_uint(As[rb + 8*LD + 4]);
            }
            #pragma unroll
            for (int j=0;j<4;j++) {
                int rb = (wn + j*8 + g)*LD + kk + tg;
                bf[j][0] = __float_as_uint(Bs[rb]);
                bf[j][1] = __float_as_uint(Bs[rb + 4]);
            }
            #pragma unroll
            for (int i=0;i<2;i++)
                #pragma unroll
                for (int j=0;j<4;j++)
                    mma_tf32(acc[i][j], af[i], bf[j]);
        }
        __syncthreads();
    }

    #pragma unroll
    for (int i=0;i<2;i++) {
        #pragma unroll
        for (int ci=0;ci<2;ci++) {
            int m = wm + i*16 + g + ci*8;
            #pragma unroll
            for (int j=0;j<4;j++) {
                #pragma unroll
                for (int cj=0;cj<2;cj++) {
                    int n = n0 + wn + j*8 + 2*tg + cj;
                    float v = acc[i][j][ci*2+cj];
                    if (n < 1024)
                        g_decpart[(long)z*BB*AD + m*AD + n] = v;
                    else if (n < 3072)
                        g_betapart[(long)z*BB*ENCD + m*ENCD + (n-1024)] = v;
                    else
                        g_gpart[(long)(4+z)*BB*G4H + m*G4H + (n-3072)] = v;
                }
            }
        }
    }
}

// ---------------------------------------------------------------
// Attention scores (grid (BB,7), 128 threads; 28 p's per block)
// ---------------------------------------------------------------
__global__ __launch_bounds__(128)
void att_score_kernel(const float* __restrict__ wfull,
                      const float* __restrict__ bfull,
                      const float* __restrict__ bdec)
{
    __shared__ float s_dec[AD];
    __shared__ float s_wf[AD];

    const int b = blockIdx.x;
    const int pbase = blockIdx.y*28;
    const int tid = threadIdx.x;
    const int warp = tid >> 5, lane = tid & 31;

    for (int i = tid; i < AD; i += 128) {
        s_dec[i] = g_decpart[b*AD + i] + g_decpart[BB*AD + b*AD + i] + bdec[i];
        s_wf[i]  = wfull[i];
    }
    __syncthreads();

    const float bf = bfull[0];
    for (int pp = warp; pp < 28; pp += 4) {
        int p = pbase + pp;
        const __half2* row = reinterpret_cast<const __half2*>(
            g_encatt_hf + ((long)b*PP + p)*AD);
        float acc = 0.f;
        #pragma unroll 4
        for (int a2 = lane; a2 < AD/2; a2 += 32) {
            __half2 e2 = row[a2];
            int a = a2*2;
            float v0 = __half2float(__low2half(e2))  + s_dec[a];
            float v1 = __half2float(__high2half(e2)) + s_dec[a+1];
            v0 = v0 > 0.f ? v0 : 0.f;
            v1 = v1 > 0.f ? v1 : 0.f;
            acc = fmaf(v0, s_wf[a], acc);
            acc = fmaf(v1, s_wf[a+1], acc);
        }
        #pragma unroll
        for (int o = 16; o > 0; o >>= 1) acc += __shfl_down_sync(0xffffffffu, acc, o);
        if (lane == 0) g_score[b*PP + p] = acc + bf;
    }
}

// softmax over PP per batch row (grid BB, 256 threads)
__global__ __launch_bounds__(256)
void softmax_kernel(float* __restrict__ out_alphas, int t)
{
    __shared__ float s_red[8];
    const int b = blockIdx.x;
    const int tid = threadIdx.x;
    const int warp = tid >> 5, lane = tid & 31;

    float v = (tid < PP) ? g_score[b*PP + tid] : -INFINITY;
    float m = v;
    #pragma unroll
    for (int o = 16; o > 0; o >>= 1) m = fmaxf(m, __shfl_xor_sync(0xffffffffu, m, o));
    if (lane == 0) s_red[warp] = m;
    __syncthreads();
    if (warp == 0) {
        float mm = (lane < 8) ? s_red[lane] : -INFINITY;
        #pragma unroll
        for (int o = 4; o > 0; o >>= 1) mm = fmaxf(mm, __shfl_xor_sync(0xffffffffu, mm, o));
        if (lane == 0) s_red[0] = mm;
    }
    __syncthreads();
    const float bmax = s_red[0];
    float e = (tid < PP) ? expf(v - bmax) : 0.f;
    float s = e;
    #pragma unroll
    for (int o = 16; o > 0; o >>= 1) s += __shfl_xor_sync(0xffffffffu, s, o);
    __syncthreads();
    if (lane == 0) s_red[warp] = s;
    __syncthreads();
    if (warp == 0) {
        float ss = (lane < 8) ? s_red[lane] : 0.f;
        #pragma unroll
        for (int o = 4; o > 0; o >>= 1) ss += __shfl_xor_sync(0xffffffffu, ss, o);
        if (lane == 0) s_red[0] = ss;
    }
    __syncthreads();
    const float inv = 1.f / s_red[0];
    if (tid < PP) {
        float al = e * inv;
        g_alpha[b*PP + tid] = al;
        float mf = (t < g_declens[b]) ? 1.f : 0.f;
        out_alphas[((long)b*TD + t)*PP + tid] = al * mf;
    }
}

// ctx+awe from fp16 eo; beta merged from 2 partials + bias.
// grid (ENCD/512, BB), 256 threads; thread handles one half2 pair.
__global__ __launch_bounds__(256)
void ctx_awe_kernel(const float* __restrict__ bbeta)
{
    __shared__ float s_al[PP];
    const int b = blockIdx.y;
    const int tid = threadIdx.x;
    if (tid < PP) s_al[tid] = g_alpha[b*PP + tid];
    __syncthreads();
    int e2 = blockIdx.x*256 + tid;
    const __half2* base = reinterpret_cast<const __half2*>(g_eohf)
                        + ((long)b*PP)*(ENCD/2) + e2;
    float a0 = 0.f, a1 = 0.f;
    #pragma unroll 4
    for (int p = 0; p < PP; p++) {
        __half2 v = base[(long)p*(ENCD/2)];
        float al = s_al[p];
        a0 = fmaf(__half2float(__low2half(v)),  al, a0);
        a1 = fmaf(__half2float(__high2half(v)), al, a1);
    }
    int e = e2*2;
    float bp0 = g_betapart[b*ENCD + e]     + g_betapart[BB*ENCD + b*ENCD + e]     + bbeta[e];
    float bp1 = g_betapart[b*ENCD + e + 1] + g_betapart[BB*ENCD + b*ENCD + e + 1] + bbeta[e+1];
    g_awe[b*ENCD + e]     = (1.f/(1.f+expf(-bp0))) * a0;
    g_awe[b*ENCD + e + 1] = (1.f/(1.f+expf(-bp1))) * a1;
}

// LSTM cell: gates = P[t] + sum of 6 partials (4 awe K-split + 2 hh K-split)
__global__ void lstm_kernel(int t)
{
    int idx = blockIdx.x*blockDim.x + threadIdx.x;
    if (idx >= BB*HD) return;
    int b = idx / HD;
    int j = idx % HD;
    long base = (long)b*G4H;
    long pbase = ((long)t*BB + b)*G4H;
    float gi = g_P[pbase + j];
    float gf = g_P[pbase + HD + j];
    float gg = g_P[pbase + 2*HD + j];
    float go = g_P[pbase + 3*HD + j];
    #pragma unroll
    for (int s = 0; s < 6; s++) {
        long pb = (long)s*BB*G4H + base;
        gi += g_gpart[pb + j];
        gf += g_gpart[pb + HD + j];
        gg += g_gpart[pb + 2*HD + j];
        go += g_gpart[pb + 3*HD + j];
    }
    float si = 1.f/(1.f+expf(-gi));
    float sf = 1.f/(1.f+expf(-gf));
    float so = 1.f/(1.f+expf(-go));
    float cn = sf * g_c[idx] + si * tanhf(gg);
    float hn = so * tanhf(cn);
    g_hall[((long)t*BB + b)*HD + j] = hn;
    if (t < g_declens[b]) { g_h[idx] = hn; g_c[idx] = cn; }
}

// ---------------------------------------------------------------
extern "C" void kernel_launch(void* const* d_in, const int* in_sizes, int n_in,
                              void* d_out, int out_size)
{
    const float* enc_out  = (const float*)d_in[0];
    const int*   caps_in  = (const int*)  d_in[1];
    const int*   lengths  = (const int*)  d_in[2];
    const float* W_enc    = (const float*)d_in[3];
    const float* b_enc    = (const float*)d_in[4];
    const float* W_dec    = (const float*)d_in[5];
    const float* b_dec    = (const float*)d_in[6];
    const float* W_full   = (const float*)d_in[7];
    const float* b_full   = (const float*)d_in[8];
    const float* emb      = (const float*)d_in[9];
    const float* W_ih     = (const float*)d_in[10];
    const float* b_ih     = (const float*)d_in[11];
    const float* W_hh     = (const float*)d_in[12];
    const float* b_hh     = (const float*)d_in[13];
    const float* W_init_h = (const float*)d_in[14];
    const float* b_init_h = (const float*)d_in[15];
    const float* W_init_c = (const float*)d_in[16];
    const float* b_init_c = (const float*)d_in[17];
    const float* W_beta   = (const float*)d_in[18];
    const float* b_beta   = (const float*)d_in[19];
    const float* W_fc     = (const float*)d_in[20];
    const float* b_fc     = (const float*)d_in[21];
    float* out = (float*)d_out;

    int *p_declens, *p_rowmap;
    float *p_mean,*p_h,*p_c,*p_hall,*p_awe,*p_gpart,*p_embt,*p_P,*p_bihh;
    __half *p_enchf;
    cudaGetSymbolAddress((void**)&p_declens, g_declens);
    cudaGetSymbolAddress((void**)&p_rowmap,  g_rowmap);
    cudaGetSymbolAddress((void**)&p_mean,    g_mean);
    cudaGetSymbolAddress((void**)&p_h,       g_h);
    cudaGetSymbolAddress((void**)&p_c,       g_c);
    cudaGetSymbolAddress((void**)&p_hall,    g_hall);
    cudaGetSymbolAddress((void**)&p_awe,     g_awe);
    cudaGetSymbolAddress((void**)&p_gpart,   g_gpart);
    cudaGetSymbolAddress((void**)&p_embt,    g_embt);
    cudaGetSymbolAddress((void**)&p_P,       g_P);
    cudaGetSymbolAddress((void**)&p_bihh,    g_bias_ihh);
    cudaGetSymbolAddress((void**)&p_enchf,   g_encatt_hf);

    // ---------- prologue ----------
    sort_kernel<<<1, 64>>>(lengths, caps_in, out);
    rowmap_kernel<<<(BB*PP + 255)/256, 256>>>();
    bias_combine_kernel<<<G4H/256, 256>>>(b_ih, b_hh);
    embt_kernel<<<(int)(((long)MB*ED + 255)/256), 256>>>(emb);
    mean_kernel<<<dim3(ENCD/256, BB), 256>>>(enc_out);
    eohf_kernel<<<(int)(((long)BB*PP*ENCD/4 + 255)/256), 256>>>(enc_out);

    // h0 / c0 : (64 x 1024), K=2048
    {
        dim3 grid(HD/64, 1, 1);
        mma_gemm64_kernel<0><<<grid, 128>>>(p_mean, ENCD, W_init_h, ENCD, b_init_h, p_h, HD, BB, HD, ENCD);
        mma_gemm64_kernel<0><<<grid, 128>>>(p_mean, ENCD, W_init_c, ENCD, b_init_c, p_c, HD, BB, HD, ENCD);
    }

    // enc_att : (12544 x 1024), K=2048 -> fp16 output (gather via rowmap)
    {
        dim3 grid(AD/128, (BB*PP)/128);
        mma_gemm128_kernel<5><<<grid, 256>>>(enc_out, p_rowmap, ENCD, W_enc, ENCD, b_enc,
                                             p_enchf, AD, BB*PP, AD, ENCD, nullptr);
    }

    // P = embt @ W_ih[:, :512]^T + (b_ih+b_hh) : (1984 x 4096), K=512
    {
        dim3 grid(G4H/128, (MB + 127)/128);
        mma_gemm128_kernel<0><<<grid, 256>>>(p_embt, nullptr, ED, W_ih, XD, p_bihh,
                                             p_P, G4H, MB, G4H, ED, nullptr);
    }

    // ---------- recurrence ----------
    for (int t = 0; t < TD; t++) {
        {
            dim3 grid((1024+2048+4096)/64, 1, 2);
            mma_hgemm_kernel<<<grid, 128>>>(W_dec, W_beta, W_hh);
        }
        att_score_kernel<<<dim3(BB, 7), 128>>>(W_full, b_full, b_dec);
        softmax_kernel<<<BB, 256>>>(out + O_ALPHA, t);
        ctx_awe_kernel<<<dim3(ENCD/512, BB), 256>>>(b_beta);
        {
            dim3 grid(G4H/64, 1, KSPL);
            mma_gemm64_kernel<6><<<grid, 128>>>(p_awe, ENCD, W_ih+ED, XD, nullptr,
                                                p_gpart, G4H, BB, G4H, KCH);
        }
        lstm_kernel<<<(BB*HD + 255)/256, 256>>>(t);
    }

    // ---------- batched predictions : (1984 x 10000), K=1024 ----------
    {
        dim3 grid((VD + 127)/128, (MB + 127)/128);
        mma_gemm128_kernel<4><<<grid, 256>>>(p_hall, nullptr, HD, W_fc, HD, b_fc,
                                             out + O_PRED, VD, MB, VD, HD, p_declens);
    }
}

// round 6
// speedup vs baseline: 5.2995x; 1.3422x over previous
#include <cuda_runtime.h>
#include <cuda_fp16.h>
#include <math.h>
#include <stdint.h>

// Problem dims
#define BB   64
#define PP   196
#define ENCD 2048
#define HD   1024
#define AD   1024
#define ED   512
#define VD   10000
#define TCD  32
#define TD   31
#define XD   (ED+ENCD)
#define G4H  (4*HD)
#define MB   (TD*BB)      // 1984
#define KSPL 4
#define KCH  (ENCD/KSPL)  // 512

// Output layout offsets (float32 elements)
#define O_PRED  0L
#define N_PRED  ((long)BB*TD*VD)
#define O_ALPHA (N_PRED)
#define N_ALPHA ((long)BB*TD*PP)
#define O_CAPS  (O_ALPHA + N_ALPHA)
#define O_DLEN  (O_CAPS + (long)BB*TCD)
#define O_IND   (O_DLEN + BB)

// -------- scratch --------
__device__ int    g_ind[BB];
__device__ int    g_declens[BB];
__device__ int    g_caps[BB*TCD];
__device__ float  g_c[BB*HD];
__device__ float  g_decpart[2*BB*AD];
__device__ float  g_betapart[2*BB*ENCD];
__device__ float  g_score[BB*PP];
__device__ float  g_gpart[6*BB*G4H];          // 0..3 awe K-split, 4..5 hh K-split
__device__ float  g_P[(long)MB*G4H];
__device__ float  g_bias_ihh[G4H];
// fp16 activations
__device__ __half g_mean_h[BB*ENCD];
__device__ __half g_hhf[BB*HD];
__device__ __half g_awehf[BB*ENCD];
__device__ __half g_hallhf[(long)MB*HD];
__device__ __half g_embt_h[(long)MB*ED];
__device__ __half g_encatt_hf[(long)BB*PP*AD];   // 25.7 MB
__device__ __half g_eohf[(long)BB*PP*ENCD];      // 51.4 MB (sorted)
// fp16 weights
__device__ __half g_Wenc_h [AD*ENCD];
__device__ __half g_Wdec_h [AD*HD];
__device__ __half g_Wbeta_h[ENCD*HD];
__device__ __half g_Whh_h  [G4H*HD];
__device__ __half g_Wih_h  [(long)G4H*XD];
__device__ __half g_Wfc_h  [(long)VD*HD];
__device__ __half g_Winh_h [HD*ENCD];
__device__ __half g_Winc_h [HD*ENCD];

__device__ __forceinline__ void mma_f16(float* c, const uint32_t* a, const uint32_t* b) {
    asm volatile("mma.sync.aligned.m16n8k16.row.col.f32.f16.f16.f32 "
                 "{%0,%1,%2,%3}, {%4,%5,%6,%7}, {%8,%9}, {%0,%1,%2,%3};"
                 : "+f"(c[0]), "+f"(c[1]), "+f"(c[2]), "+f"(c[3])
                 : "r"(a[0]), "r"(a[1]), "r"(a[2]), "r"(a[3]),
                   "r"(b[0]), "r"(b[1]));
}

// ---------------------------------------------------------------
// small kernels
// ---------------------------------------------------------------
__global__ void sort_kernel(const int* __restrict__ lengths,
                            const int* __restrict__ caps_in,
                            float* __restrict__ out)
{
    int b = threadIdx.x;
    if (b < BB) {
        int len = lengths[b];
        int rank = 0;
        for (int b2 = 0; b2 < BB; b2++) {
            int l2 = lengths[b2];
            rank += (l2 > len) || (l2 == len && b2 < b);
        }
        g_ind[rank] = b;
    }
    __syncthreads();
    if (b < BB) {
        int i = g_ind[b];
        int dl = lengths[i] - 1;
        g_declens[b] = dl;
        out[O_DLEN + b] = (float)dl;
        out[O_IND  + b] = (float)i;
        for (int j = 0; j < TCD; j++) {
            int cv = caps_in[i*TCD + j];
            g_caps[b*TCD + j] = cv;
            out[O_CAPS + b*TCD + j] = (float)cv;
        }
    }
}

__global__ void bias_combine_kernel(const float* __restrict__ b_ih,
                                    const float* __restrict__ b_hh)
{
    int n = blockIdx.x*blockDim.x + threadIdx.x;
    if (n < G4H) g_bias_ihh[n] = b_ih[n] + b_hh[n];
}

// f32 -> f16 conversion (grid-stride over float4)
__global__ void cvt_kernel(const float* __restrict__ src, __half* __restrict__ dst, long n4)
{
    long i = (long)blockIdx.x*blockDim.x + threadIdx.x;
    if (i >= n4) return;
    const float4 v = reinterpret_cast<const float4*>(src)[i];
    __half2 o0 = __floats2half2_rn(v.x, v.y);
    __half2 o1 = __floats2half2_rn(v.z, v.w);
    reinterpret_cast<__half2*>(dst)[i*2]   = o0;
    reinterpret_cast<__half2*>(dst)[i*2+1] = o1;
}

__global__ void embt_kernel(const float* __restrict__ emb)
{
    long idx = (long)blockIdx.x*blockDim.x + threadIdx.x;
    if (idx >= (long)MB*ED) return;
    int row = (int)(idx / ED), j = (int)(idx % ED);
    int t = row / BB, b = row % BB;
    int cap = g_caps[b*TCD + t];
    g_embt_h[idx] = __float2half(emb[(long)cap*ED + j]);
}

__global__ void mean_kernel(const float* __restrict__ enc_out)
{
    int e = blockIdx.x*blockDim.x + threadIdx.x;
    int b = blockIdx.y;
    if (e >= ENCD) return;
    long base = ((long)g_ind[b]*PP)*ENCD + e;
    float acc = 0.f;
    for (int p = 0; p < PP; p++) acc += enc_out[base + (long)p*ENCD];
    g_mean_h[b*ENCD + e] = __float2half(acc / (float)PP);
}

// sorted eo -> fp16
__global__ void eohf_kernel(const float* __restrict__ enc_out)
{
    long idx4 = ((long)blockIdx.x*blockDim.x + threadIdx.x);
    if (idx4 >= (long)BB*PP*ENCD/4) return;
    long idx = idx4*4;
    int b = (int)(idx / ((long)PP*ENCD));
    long rem = idx - (long)b*PP*ENCD;
    const float4 v = *reinterpret_cast<const float4*>(enc_out + (long)g_ind[b]*PP*ENCD + rem);
    *reinterpret_cast<__half2*>(g_eohf + idx)     = __floats2half2_rn(v.x, v.y);
    *reinterpret_cast<__half2*>(g_eohf + idx + 2) = __floats2half2_rn(v.z, v.w);
}

// ---------------------------------------------------------------
// FP16 64x64 GEMM (4 warps, BK=32, m16n8k16):
//  EPI 0: fp32 write + bias
//  EPI 5: fp16 write + bias
//  EPI 6: K-split partial fp32 (zoff)
// ---------------------------------------------------------------
template<int EPI>
__global__ __launch_bounds__(128)
void fgemm64_kernel(const __half* __restrict__ A, int lda,
                    const __half* __restrict__ W, int ldw,
                    const float* __restrict__ bias,
                    void* __restrict__ Cv, int ldc,
                    int M, int N, int K)
{
    constexpr int BM=64, BN=64, BK=32, LD=BK+8, NT=128;
    __shared__ __half As[BM*LD];
    __shared__ __half Bs[BN*LD];

    const int tid = threadIdx.x;
    const int m0 = blockIdx.y*BM, n0 = blockIdx.x*BN;
    const long kbase = (long)blockIdx.z * K;
    const int warp = tid >> 5, lane = tid & 31;
    const int wm = (warp % 2)*32, wn = (warp / 2)*32;
    const int g = lane >> 2, tg = lane & 3;

    float acc[2][4][4];
    #pragma unroll
    for (int i=0;i<2;i++)
        #pragma unroll
        for (int j=0;j<4;j++)
            #pragma unroll
            for (int q=0;q<4;q++) acc[i][j][q]=0.f;

    for (int k0 = 0; k0 < K; k0 += BK) {
        #pragma unroll
        for (int s = tid; s < BM*(BK/8); s += NT) {
            int r  = s / (BK/8);
            int kk = (s % (BK/8))*8;
            int row = m0 + r;
            float4 v = make_float4(0.f,0.f,0.f,0.f);
            if (row < M) v = *reinterpret_cast<const float4*>(A + (long)row*lda + kbase + k0 + kk);
            *reinterpret_cast<float4*>(&As[r*LD + kk]) = v;
        }
        #pragma unroll
        for (int s = tid; s < BN*(BK/8); s += NT) {
            int r  = s / (BK/8);
            int kk = (s % (BK/8))*8;
            int n = n0 + r;
            float4 v = make_float4(0.f,0.f,0.f,0.f);
            if (n < N) v = *reinterpret_cast<const float4*>(W + (long)n*ldw + kbase + k0 + kk);
            *reinterpret_cast<float4*>(&Bs[r*LD + kk]) = v;
        }
        __syncthreads();
        #pragma unroll
        for (int kk = 0; kk < BK; kk += 16) {
            uint32_t af[2][4], bf[4][2];
            #pragma unroll
            for (int i=0;i<2;i++) {
                int r0 = (wm + i*16 + g)*LD + kk + 2*tg;
                int r1 = (wm + i*16 + g + 8)*LD + kk + 2*tg;
                af[i][0] = *reinterpret_cast<const uint32_t*>(&As[r0]);
                af[i][1] = *reinterpret_cast<const uint32_t*>(&As[r1]);
                af[i][2] = *reinterpret_cast<const uint32_t*>(&As[r0 + 8]);
                af[i][3] = *reinterpret_cast<const uint32_t*>(&As[r1 + 8]);
            }
            #pragma unroll
            for (int j=0;j<4;j++) {
                int rb = (wn + j*8 + g)*LD + kk + 2*tg;
                bf[j][0] = *reinterpret_cast<const uint32_t*>(&Bs[rb]);
                bf[j][1] = *reinterpret_cast<const uint32_t*>(&Bs[rb + 8]);
            }
            #pragma unroll
            for (int i=0;i<2;i++)
                #pragma unroll
                for (int j=0;j<4;j++)
                    mma_f16(acc[i][j], af[i], bf[j]);
        }
        __syncthreads();
    }

    float* Cf = (float*)Cv;
    __half* Ch = (__half*)Cv;
    const long zoff = (EPI == 6) ? (long)blockIdx.z * M * ldc : 0;
    #pragma unroll
    for (int i=0;i<2;i++) {
        #pragma unroll
        for (int ci=0;ci<2;ci++) {
            int m = m0 + wm + i*16 + g + ci*8;
            if (m >= M) continue;
            #pragma unroll
            for (int j=0;j<4;j++) {
                #pragma unroll
                for (int cj=0;cj<2;cj++) {
                    int n = n0 + wn + j*8 + 2*tg + cj;
                    if (n >= N) continue;
                    float v = acc[i][j][ci*2+cj];
                    if      (EPI == 0) Cf[(long)m*ldc + n] = v + bias[n];
                    else if (EPI == 5) Ch[(long)m*ldc + n] = __float2half(v + bias[n]);
                    else               Cf[zoff + (long)m*ldc + n] = v;
                }
            }
        }
    }
}

// ---------------------------------------------------------------
// FP16 128x128 GEMM (8 warps, warp tile 32x64):
//  EPI 0: fp32 write + bias
//  EPI 4: preds scatter (m=t*BB+b -> row b*TD+t) * mask
//  EPI 5: fp16 write + bias
// ---------------------------------------------------------------
template<int EPI>
__global__ __launch_bounds__(256)
void fgemm128_kernel(const __half* __restrict__ A, int lda,
                     const __half* __restrict__ W, int ldw,
                     const float* __restrict__ bias,
                     void* __restrict__ Cv, int ldc,
                     int M, int N, int K,
                     const int* __restrict__ declens)
{
    constexpr int BM=128, BN=128, BK=32, LD=BK+8, NT=256;
    __shared__ __half As[BM*LD];
    __shared__ __half Bs[BN*LD];

    const int tid = threadIdx.x;
    const int m0 = blockIdx.y*BM, n0 = blockIdx.x*BN;
    const int warp = tid >> 5, lane = tid & 31;
    const int wm = (warp % 4)*32, wn = (warp / 4)*64;
    const int g = lane >> 2, tg = lane & 3;

    float acc[2][8][4];
    #pragma unroll
    for (int i=0;i<2;i++)
        #pragma unroll
        for (int j=0;j<8;j++)
            #pragma unroll
            for (int q=0;q<4;q++) acc[i][j][q]=0.f;

    for (int k0 = 0; k0 < K; k0 += BK) {
        #pragma unroll
        for (int s = tid; s < BM*(BK/8); s += NT) {
            int r  = s / (BK/8);
            int kk = (s % (BK/8))*8;
            int row = m0 + r;
            float4 v = make_float4(0.f,0.f,0.f,0.f);
            if (row < M) v = *reinterpret_cast<const float4*>(A + (long)row*lda + k0 + kk);
            *reinterpret_cast<float4*>(&As[r*LD + kk]) = v;
        }
        #pragma unroll
        for (int s = tid; s < BN*(BK/8); s += NT) {
            int r  = s / (BK/8);
            int kk = (s % (BK/8))*8;
            int n = n0 + r;
            float4 v = make_float4(0.f,0.f,0.f,0.f);
            if (n < N) v = *reinterpret_cast<const float4*>(W + (long)n*ldw + k0 + kk);
            *reinterpret_cast<float4*>(&Bs[r*LD + kk]) = v;
        }
        __syncthreads();
        #pragma unroll
        for (int kk = 0; kk < BK; kk += 16) {
            uint32_t af[2][4], bf[8][2];
            #pragma unroll
            for (int i=0;i<2;i++) {
                int r0 = (wm + i*16 + g)*LD + kk + 2*tg;
                int r1 = (wm + i*16 + g + 8)*LD + kk + 2*tg;
                af[i][0] = *reinterpret_cast<const uint32_t*>(&As[r0]);
                af[i][1] = *reinterpret_cast<const uint32_t*>(&As[r1]);
                af[i][2] = *reinterpret_cast<const uint32_t*>(&As[r0 + 8]);
                af[i][3] = *reinterpret_cast<const uint32_t*>(&As[r1 + 8]);
            }
            #pragma unroll
            for (int j=0;j<8;j++) {
                int rb = (wn + j*8 + g)*LD + kk + 2*tg;
                bf[j][0] = *reinterpret_cast<const uint32_t*>(&Bs[rb]);
                bf[j][1] = *reinterpret_cast<const uint32_t*>(&Bs[rb + 8]);
            }
            #pragma unroll
            for (int i=0;i<2;i++)
                #pragma unroll
                for (int j=0;j<8;j++)
                    mma_f16(acc[i][j], af[i], bf[j]);
        }
        __syncthreads();
    }

    float* Cf = (float*)Cv;
    __half* Ch = (__half*)Cv;
    #pragma unroll
    for (int i=0;i<2;i++) {
        #pragma unroll
        for (int ci=0;ci<2;ci++) {
            int m = m0 + wm + i*16 + g + ci*8;
            if (m >= M) continue;
            float mf = 1.f; long orow = (long)m;
            if (EPI == 4) {
                int tt = m / BB, bb = m % BB;
                mf = (tt < declens[bb]) ? 1.f : 0.f;
                orow = (long)bb*TD + tt;
            }
            #pragma unroll
            for (int j=0;j<8;j++) {
                #pragma unroll
                for (int cj=0;cj<2;cj++) {
                    int n = n0 + wn + j*8 + 2*tg + cj;
                    if (n >= N) continue;
                    float v = acc[i][j][ci*2+cj] + bias[n];
                    if      (EPI == 0) Cf[(long)m*ldc + n] = v;
                    else if (EPI == 4) Cf[orow*ldc + n] = v * mf;
                    else               Ch[(long)m*ldc + n] = __float2half(v);
                }
            }
        }
    }
}

// ---------------------------------------------------------------
// Per-step h-GEMM fp16, K-split (grid.z in {0,1}):
// weights concat along N: [W_dec(1024) | W_beta(2048) | W_hh(4096)] (fp16)
// ---------------------------------------------------------------
__global__ __launch_bounds__(128)
void hstep_kernel()
{
    constexpr int BM=64, BN=64, BK=32, LD=BK+8, NT=128, KC=HD/2;
    __shared__ __half As[BM*LD];
    __shared__ __half Bs[BN*LD];

    const int tid = threadIdx.x;
    const int n0 = blockIdx.x*BN;
    const int z = blockIdx.z;
    const long kbase = (long)z*KC;
    const int warp = tid >> 5, lane = tid & 31;
    const int wm = (warp % 2)*32, wn = (warp / 2)*32;
    const int g = lane >> 2, tg = lane & 3;

    float acc[2][4][4];
    #pragma unroll
    for (int i=0;i<2;i++)
        #pragma unroll
        for (int j=0;j<4;j++)
            #pragma unroll
            for (int q=0;q<4;q++) acc[i][j][q]=0.f;

    for (int k0 = 0; k0 < KC; k0 += BK) {
        #pragma unroll
        for (int s = tid; s < BM*(BK/8); s += NT) {
            int r  = s / (BK/8);
            int kk = (s % (BK/8))*8;
            float4 v = *reinterpret_cast<const float4*>(g_hhf + (long)r*HD + kbase + k0 + kk);
            *reinterpret_cast<float4*>(&As[r*LD + kk]) = v;
        }
        #pragma unroll
        for (int s = tid; s < BN*(BK/8); s += NT) {
            int r  = s / (BK/8);
            int kk = (s % (BK/8))*8;
            int gn = n0 + r;
            const __half* wrow;
            if (gn < 1024)      wrow = g_Wdec_h  + (long)gn*HD;
            else if (gn < 3072) wrow = g_Wbeta_h + (long)(gn-1024)*HD;
            else                wrow = g_Whh_h   + (long)(gn-3072)*HD;
            float4 v = *reinterpret_cast<const float4*>(wrow + kbase + k0 + kk);
            *reinterpret_cast<float4*>(&Bs[r*LD + kk]) = v;
        }
        __syncthreads();
        #pragma unroll
        for (int kk = 0; kk < BK; kk += 16) {
            uint32_t af[2][4], bf[4][2];
            #pragma unroll
            for (int i=0;i<2;i++) {
                int r0 = (wm + i*16 + g)*LD + kk + 2*tg;
                int r1 = (wm + i*16 + g + 8)*LD + kk + 2*tg;
                af[i][0] = *reinterpret_cast<const uint32_t*>(&As[r0]);
                af[i][1] = *reinterpret_cast<const uint32_t*>(&As[r1]);
                af[i][2] = *reinterpret_cast<const uint32_t*>(&As[r0 + 8]);
                af[i][3] = *reinterpret_cast<const uint32_t*>(&As[r1 + 8]);
            }
            #pragma unroll
            for (int j=0;j<4;j++) {
                int rb = (wn + j*8 + g)*LD + kk + 2*tg;
                bf[j][0] = *reinterpret_cast<const uint32_t*>(&Bs[rb]);
                bf[j][1] = *reinterpret_cast<const uint32_t*>(&Bs[rb + 8]);
            }
            #pragma unroll
            for (int i=0;i<2;i++)
                #pragma unroll
                for (int j=0;j<4;j++)
                    mma_f16(acc[i][j], af[i], bf[j]);
        }
        __syncthreads();
    }

    #pragma unroll
    for (int i=0;i<2;i++) {
        #pragma unroll
        for (int ci=0;ci<2;ci++) {
            int m = wm + i*16 + g + ci*8;
            #pragma unroll
            for (int j=0;j<4;j++) {
                #pragma unroll
                for (int cj=0;cj<2;cj++) {
                    int n = n0 + wn + j*8 + 2*tg + cj;
                    float v = acc[i][j][ci*2+cj];
                    if (n < 1024)
                        g_decpart[(long)z*BB*AD + m*AD + n] = v;
                    else if (n < 3072)
                        g_betapart[(long)z*BB*ENCD + m*ENCD + (n-1024)] = v;
                    else
                        g_gpart[(long)(4+z)*BB*G4H + m*G4H + (n-3072)] = v;
                }
            }
        }
    }
}

// ---------------------------------------------------------------
// Attention scores (grid (BB,7), 128 threads; 28 p's per block)
// ---------------------------------------------------------------
__global__ __launch_bounds__(128)
void att_score_kernel(const float* __restrict__ wfull,
                      const float* __restrict__ bfull,
                      const float* __restrict__ bdec)
{
    __shared__ float s_dec[AD];
    __shared__ float s_wf[AD];

    const int b = blockIdx.x;
    const int pbase = blockIdx.y*28;
    const int tid = threadIdx.x;
    const int warp = tid >> 5, lane = tid & 31;

    for (int i = tid; i < AD; i += 128) {
        s_dec[i] = g_decpart[b*AD + i] + g_decpart[BB*AD + b*AD + i] + bdec[i];
        s_wf[i]  = wfull[i];
    }
    __syncthreads();

    const float bf = bfull[0];
    for (int pp = warp; pp < 28; pp += 4) {
        int p = pbase + pp;
        const __half2* row = reinterpret_cast<const __half2*>(
            g_encatt_hf + ((long)b*PP + p)*AD);
        float acc = 0.f;
        #pragma unroll 4
        for (int a2 = lane; a2 < AD/2; a2 += 32) {
            __half2 e2 = row[a2];
            int a = a2*2;
            float v0 = __half2float(__low2half(e2))  + s_dec[a];
            float v1 = __half2float(__high2half(e2)) + s_dec[a+1];
            v0 = v0 > 0.f ? v0 : 0.f;
            v1 = v1 > 0.f ? v1 : 0.f;
            acc = fmaf(v0, s_wf[a], acc);
            acc = fmaf(v1, s_wf[a+1], acc);
        }
        #pragma unroll
        for (int o = 16; o > 0; o >>= 1) acc += __shfl_down_sync(0xffffffffu, acc, o);
        if (lane == 0) g_score[b*PP + p] = acc + bf;
    }
}

// ---------------------------------------------------------------
// Fused softmax + context + awe. grid (ENCD/512, BB), 256 threads.
// Each block redundantly softmaxes the 196 cached scores (cheap),
// then computes its 512-wide e-chunk of context and writes fp16 awe.
// Block x==0 also writes masked alphas to output.
// ---------------------------------------------------------------
__global__ __launch_bounds__(256)
void ctx_awe_kernel(const float* __restrict__ bbeta,
                    float* __restrict__ out_alphas, int t)
{
    __shared__ float s_al[PP];
    __shared__ float s_red[8];
    const int b = blockIdx.y;
    const int tid = threadIdx.x;
    const int warp = tid >> 5, lane = tid & 31;

    // softmax over the 196 scores
    float v = (tid < PP) ? g_score[b*PP + tid] : -INFINITY;
    float m = v;
    #pragma unroll
    for (int o = 16; o > 0; o >>= 1) m = fmaxf(m, __shfl_xor_sync(0xffffffffu, m, o));
    if (lane == 0) s_red[warp] = m;
    __syncthreads();
    if (warp == 0) {
        float mm = (lane < 8) ? s_red[lane] : -INFINITY;
        #pragma unroll
        for (int o = 4; o > 0; o >>= 1) mm = fmaxf(mm, __shfl_xor_sync(0xffffffffu, mm, o));
        if (lane == 0) s_red[0] = mm;
    }
    __syncthreads();
    const float bmax = s_red[0];
    float e = (tid < PP) ? expf(v - bmax) : 0.f;
    float s = e;
    #pragma unroll
    for (int o = 16; o > 0; o >>= 1) s += __shfl_xor_sync(0xffffffffu, s, o);
    if (lane == 0) s_red[warp] = s;
    __syncthreads();
    if (warp == 0) {
        float ss = (lane < 8) ? s_red[lane] : 0.f;
        #pragma unroll
        for (int o = 4; o > 0; o >>= 1) ss += __shfl_xor_sync(0xffffffffu, ss, o);
        if (lane == 0) s_red[0] = ss;
    }
    __syncthreads();
    const float inv = 1.f / s_red[0];
    if (tid < PP) {
        float al = e * inv;
        s_al[tid] = al;
        if (blockIdx.x == 0) {
            float mf = (t < g_declens[b]) ? 1.f : 0.f;
            out_alphas[((long)b*TD + t)*PP + tid] = al * mf;
        }
    }
    __syncthreads();

    // context + awe
    int e2 = blockIdx.x*256 + tid;
    const __half2* base = reinterpret_cast<const __half2*>(g_eohf)
                        + ((long)b*PP)*(ENCD/2) + e2;
    float a0 = 0.f, a1 = 0.f;
    #pragma unroll 4
    for (int p = 0; p < PP; p++) {
        __half2 vv = base[(long)p*(ENCD/2)];
        float al = s_al[p];
        a0 = fmaf(__half2float(__low2half(vv)),  al, a0);
        a1 = fmaf(__half2float(__high2half(vv)), al, a1);
    }
    int ee = e2*2;
    float bp0 = g_betapart[b*ENCD + ee]     + g_betapart[BB*ENCD + b*ENCD + ee]     + bbeta[ee];
    float bp1 = g_betapart[b*ENCD + ee + 1] + g_betapart[BB*ENCD + b*ENCD + ee + 1] + bbeta[ee+1];
    float w0 = (1.f/(1.f+expf(-bp0))) * a0;
    float w1 = (1.f/(1.f+expf(-bp1))) * a1;
    *reinterpret_cast<__half2*>(g_awehf + b*ENCD + ee) = __floats2half2_rn(w0, w1);
}

// LSTM cell: gates = P[t] + 6 partials; fp16 h state + fp16 hall
__global__ void lstm_kernel(int t)
{
    int idx = blockIdx.x*blockDim.x + threadIdx.x;
    if (idx >= BB*HD) return;
    int b = idx / HD;
    int j = idx % HD;
    long base = (long)b*G4H;
    long pbase = ((long)t*BB + b)*G4H;
    float gi = g_P[pbase + j];
    float gf = g_P[pbase + HD + j];
    float gg = g_P[pbase + 2*HD + j];
    float go = g_P[pbase + 3*HD + j];
    #pragma unroll
    for (int s = 0; s < 6; s++) {
        long pb = (long)s*BB*G4H + base;
        gi += g_gpart[pb + j];
        gf += g_gpart[pb + HD + j];
        gg += g_gpart[pb + 2*HD + j];
        go += g_gpart[pb + 3*HD + j];
    }
    float si = 1.f/(1.f+expf(-gi));
    float sf = 1.f/(1.f+expf(-gf));
    float so = 1.f/(1.f+expf(-go));
    float cn = sf * g_c[idx] + si * tanhf(gg);
    float hn = so * tanhf(cn);
    g_hallhf[((long)t*BB + b)*HD + j] = __float2half(hn);
    if (t < g_declens[b]) { g_hhf[idx] = __float2half(hn); g_c[idx] = cn; }
}

// ---------------------------------------------------------------
extern "C" void kernel_launch(void* const* d_in, const int* in_sizes, int n_in,
                              void* d_out, int out_size)
{
    const float* enc_out  = (const float*)d_in[0];
    const int*   caps_in  = (const int*)  d_in[1];
    const int*   lengths  = (const int*)  d_in[2];
    const float* W_enc    = (const float*)d_in[3];
    const float* b_enc    = (const float*)d_in[4];
    const float* W_dec    = (const float*)d_in[5];
    const float* b_dec    = (const float*)d_in[6];
    const float* W_full   = (const float*)d_in[7];
    const float* b_full   = (const float*)d_in[8];
    const float* emb      = (const float*)d_in[9];
    const float* W_ih     = (const float*)d_in[10];
    const float* b_ih     = (const float*)d_in[11];
    const float* W_hh     = (const float*)d_in[12];
    const float* b_hh     = (const float*)d_in[13];
    const float* W_init_h = (const float*)d_in[14];
    const float* b_init_h = (const float*)d_in[15];
    const float* W_init_c = (const float*)d_in[16];
    const float* b_init_c = (const float*)d_in[17];
    const float* W_beta   = (const float*)d_in[18];
    const float* b_beta   = (const float*)d_in[19];
    const float* W_fc     = (const float*)d_in[20];
    const float* b_fc     = (const float*)d_in[21];
    float* out = (float*)d_out;

    int *p_declens;
    float *p_c,*p_gpart,*p_P,*p_bihh;
    __half *p_meanh,*p_hhf,*p_awehf,*p_hallhf,*p_embth,*p_enchf,*p_eohf;
    __half *p_Wenc,*p_Wdec,*p_Wbeta,*p_Whh,*p_Wih,*p_Wfc,*p_Winh,*p_Winc;
    cudaGetSymbolAddress((void**)&p_declens, g_declens);
    cudaGetSymbolAddress((void**)&p_c,       g_c);
    cudaGetSymbolAddress((void**)&p_gpart,   g_gpart);
    cudaGetSymbolAddress((void**)&p_P,       g_P);
    cudaGetSymbolAddress((void**)&p_bihh,    g_bias_ihh);
    cudaGetSymbolAddress((void**)&p_meanh,   g_mean_h);
    cudaGetSymbolAddress((void**)&p_hhf,     g_hhf);
    cudaGetSymbolAddress((void**)&p_awehf,   g_awehf);
    cudaGetSymbolAddress((void**)&p_hallhf,  g_hallhf);
    cudaGetSymbolAddress((void**)&p_embth,   g_embt_h);
    cudaGetSymbolAddress((void**)&p_enchf,   g_encatt_hf);
    cudaGetSymbolAddress((void**)&p_eohf,    g_eohf);
    cudaGetSymbolAddress((void**)&p_Wenc,    g_Wenc_h);
    cudaGetSymbolAddress((void**)&p_Wdec,    g_Wdec_h);
    cudaGetSymbolAddress((void**)&p_Wbeta,   g_Wbeta_h);
    cudaGetSymbolAddress((void**)&p_Whh,     g_Whh_h);
    cudaGetSymbolAddress((void**)&p_Wih,     g_Wih_h);
    cudaGetSymbolAddress((void**)&p_Wfc,     g_Wfc_h);
    cudaGetSymbolAddress((void**)&p_Winh,    g_Winh_h);
    cudaGetSymbolAddress((void**)&p_Winc,    g_Winc_h);

    auto cvt = [](const float* src, __half* dst, long n) {
        long n4 = n/4;
        cvt_kernel<<<(int)((n4 + 255)/256), 256>>>(src, dst, n4);
    };

    // ---------- prologue ----------
    sort_kernel<<<1, 64>>>(lengths, caps_in, out);
    bias_combine_kernel<<<G4H/256, 256>>>(b_ih, b_hh);
    cvt(W_enc,    p_Wenc,  (long)AD*ENCD);
    cvt(W_dec,    p_Wdec,  (long)AD*HD);
    cvt(W_beta,   p_Wbeta, (long)ENCD*HD);
    cvt(W_hh,     p_Whh,   (long)G4H*HD);
    cvt(W_ih,     p_Wih,   (long)G4H*XD);
    cvt(W_fc,     p_Wfc,   (long)VD*HD);
    cvt(W_init_h, p_Winh,  (long)HD*ENCD);
    cvt(W_init_c, p_Winc,  (long)HD*ENCD);
    embt_kernel<<<(int)(((long)MB*ED + 255)/256), 256>>>(emb);
    mean_kernel<<<dim3(ENCD/256, BB), 256>>>(enc_out);
    eohf_kernel<<<(int)(((long)BB*PP*ENCD/4 + 255)/256), 256>>>(enc_out);

    // h0 (fp16 out) / c0 (fp32 out) : (64 x 1024), K=2048
    {
        dim3 grid(HD/64, 1, 1);
        fgemm64_kernel<5><<<grid, 128>>>(p_meanh, ENCD, p_Winh, ENCD, b_init_h, p_hhf, HD, BB, HD, ENCD);
        fgemm64_kernel<0><<<grid, 128>>>(p_meanh, ENCD, p_Winc, ENCD, b_init_c, p_c,   HD, BB, HD, ENCD);
    }

    // enc_att : (12544 x 1024), K=2048, A = sorted fp16 eo -> fp16 out
    {
        dim3 grid(AD/128, (BB*PP)/128);
        fgemm128_kernel<5><<<grid, 256>>>(p_eohf, ENCD, p_Wenc, ENCD, b_enc,
                                          p_enchf, AD, BB*PP, AD, ENCD, nullptr);
    }

    // P = embt @ W_ih[:, :512]^T + (b_ih+b_hh) : (1984 x 4096), K=512
    {
        dim3 grid(G4H/128, (MB + 127)/128);
        fgemm128_kernel<0><<<grid, 256>>>(p_embth, ED, p_Wih, XD, p_bihh,
                                          p_P, G4H, MB, G4H, ED, nullptr);
    }

    // ---------- recurrence ----------
    for (int t = 0; t < TD; t++) {
        {
            dim3 grid((1024+2048+4096)/64, 1, 2);
            hstep_kernel<<<grid, 128>>>();
        }
        att_score_kernel<<<dim3(BB, 7), 128>>>(W_full, b_full, b_dec);
        ctx_awe_kernel<<<dim3(ENCD/512, BB), 256>>>(b_beta, out + O_ALPHA, t);
        {
            dim3 grid(G4H/64, 1, KSPL);
            fgemm64_kernel<6><<<grid, 128>>>(p_awehf, ENCD, p_Wih + ED, XD, nullptr,
                                             p_gpart, G4H, BB, G4H, KCH);
        }
        lstm_kernel<<<(BB*HD + 255)/256, 256>>>(t);
    }

    // ---------- batched predictions : (1984 x 10000), K=1024 ----------
    {
        dim3 grid((VD + 127)/128, (MB + 127)/128);
        fgemm128_kernel<4><<<grid, 256>>>(p_hallhf, HD, p_Wfc, HD, b_fc,
                                          out + O_PRED, VD, MB, VD, HD, p_declens);
    }
}